// round 13
// baseline (speedup 1.0000x reference)
#include <cuda_runtime.h>
#include <cuda_bf16.h>
#include <cstdint>
#include <cstddef>

#define NN 100000
#define EDGES_MAX 800000
#define NBLD 148
#define TBLD 1024
#define NPB ((NN + NBLD - 1) / NBLD)

// ---------------- scratch (static __device__, no allocation) ----------------
__device__ __align__(256) __nv_bfloat16 g_A1h[(size_t)NN * 128];
__device__ __align__(256) __nv_bfloat16 g_A1l[(size_t)NN * 128];
__device__ __align__(256) __nv_bfloat16 g_X1h[(size_t)NN * 256];
__device__ __align__(256) __nv_bfloat16 g_X1l[(size_t)NN * 256];
__device__ __align__(256) __nv_bfloat16 g_X2h[(size_t)NN * 128];
__device__ __align__(256) __nv_bfloat16 g_X2l[(size_t)NN * 128];
__device__ __align__(256) float g_T2[NN * 128];
__device__ __align__(256) float g_T3[NN * 40];
__device__ __align__(256) float g_invout[NN];
__device__ __align__(256) float g_invin[NN];
__device__ __align__(256) int g_odegi[NN];
__device__ __align__(256) int g_idegi[NN];
__device__ __align__(256) int g_rowstart[NN];
__device__ __align__(256) int g_ctr[NN];
__device__ __align__(256) int g_blocksum[NBLD];
__device__ __align__(256) int g_csr[EDGES_MAX];
__device__ unsigned g_barC;
__device__ __align__(256) __nv_bfloat16 g_Wt1h[256 * 128];
__device__ __align__(256) __nv_bfloat16 g_Wt1l[256 * 128];
__device__ __align__(256) __nv_bfloat16 g_Wt2h[128 * 256];
__device__ __align__(256) __nv_bfloat16 g_Wt2l[128 * 256];
__device__ __align__(256) __nv_bfloat16 g_Wt3h[40 * 128];
__device__ __align__(256) __nv_bfloat16 g_Wt3l[40 * 128];

__device__ __forceinline__ uint32_t pack_bf2(float x, float y) {
    __nv_bfloat162 t = __floats2bfloat162_rn(x, y);
    return *reinterpret_cast<uint32_t*>(&t);
}
__device__ __forceinline__ void split2(float x, float y, uint32_t& hi, uint32_t& lo) {
    __nv_bfloat162 h = __floats2bfloat162_rn(x, y);
    float rx = x - __bfloat162float(h.x);
    float ry = y - __bfloat162float(h.y);
    hi = *reinterpret_cast<uint32_t*>(&h);
    lo = pack_bf2(rx, ry);
}

// ---------------- fused build kernel ----------------
__device__ __forceinline__ void grid_bar() {
    __syncthreads();
    __threadfence();
    if (threadIdx.x == 0) {
        unsigned old = atomicAdd(&g_barC, 1u);
        unsigned target = (old / NBLD + 1u) * NBLD;
        while (*(volatile unsigned*)&g_barC < target) { __nanosleep(64); }
    }
    __syncthreads();
}

__device__ __forceinline__ void wsplit_one(const float* __restrict__ W, int K, int N, int i,
                                           __nv_bfloat16* __restrict__ th,
                                           __nv_bfloat16* __restrict__ tl) {
    int k = i / N, n = i % N;
    float w = W[i];
    __nv_bfloat16 h = __float2bfloat16(w);
    float r = w - __bfloat162float(h);
    th[n * K + k] = h;
    tl[n * K + k] = __float2bfloat16(r);
}

__global__ __launch_bounds__(TBLD, 1)
void build_kernel(const int* __restrict__ src, const int* __restrict__ dst, int E,
                  const float* __restrict__ W1, const float* __restrict__ W2,
                  const float* __restrict__ W3) {
    __shared__ int sm_scan[TBLD];
    __shared__ int sm_bs[NBLD];

    const int t = threadIdx.x;
    const int b = blockIdx.x;
    const int gi = b * TBLD + t;

    if (gi < NN) { g_odegi[gi] = 0; g_idegi[gi] = 0; }
    if (gi < 128 * 256) {
        wsplit_one(W1, 128, 256, gi, g_Wt1h, g_Wt1l);
        wsplit_one(W2, 256, 128, gi, g_Wt2h, g_Wt2l);
    }
    if (gi < 128 * 40) wsplit_one(W3, 128, 40, gi, g_Wt3h, g_Wt3l);
    grid_bar();

    for (int e = gi; e < E; e += NBLD * TBLD) {
        atomicAdd(&g_odegi[src[e]], 1);
        atomicAdd(&g_idegi[dst[e]], 1);
    }
    grid_bar();

    const int node = b * NPB + t;
    const int deg = (t < NPB && node < NN) ? g_idegi[node] : 0;
    sm_scan[t] = deg;
    __syncthreads();
    #pragma unroll
    for (int off = 1; off < TBLD; off <<= 1) {
        int a = (t >= off) ? sm_scan[t - off] : 0;
        __syncthreads();
        sm_scan[t] += a;
        __syncthreads();
    }
    const int incl = sm_scan[t];
    if (t == 0) g_blocksum[b] = sm_scan[TBLD - 1];
    grid_bar();

    if (t < NBLD) sm_bs[t] = g_blocksum[t];
    __syncthreads();
    int off = 0;
    for (int j = 0; j < b; ++j) off += sm_bs[j];
    if (t < NPB && node < NN) {
        int rs = off + incl - deg;
        g_rowstart[node] = rs;
        g_ctr[node] = rs;
        g_invout[node] = rsqrtf(fmaxf((float)g_odegi[node], 1.0f));
        g_invin[node]  = rsqrtf(fmaxf((float)deg, 1.0f));
    }
    grid_bar();

    for (int e = gi; e < E; e += NBLD * TBLD) {
        int p = atomicAdd(&g_ctr[dst[e]], 1);
        g_csr[p] = src[e];
    }
}

// ---------------- CSR gather aggregation ----------------
template <int F4, int MODE>
__global__ __launch_bounds__(256)
void agg_kernel(const float* __restrict__ H, const int* __restrict__ csr,
                const int* __restrict__ rowstart, const int* __restrict__ degi,
                const float* __restrict__ pre, const float* __restrict__ invin,
                const float* __restrict__ bias, const float* __restrict__ invout2,
                float* __restrict__ outf,
                __nv_bfloat16* __restrict__ outh, __nv_bfloat16* __restrict__ outl,
                int n) {
    int w = (blockIdx.x * blockDim.x + threadIdx.x) >> 5;
    if (w >= n) return;
    int lane = threadIdx.x & 31;
    int start = rowstart[w];
    int deg = degi[w];

    float4 acc = make_float4(0.f, 0.f, 0.f, 0.f);
    const float4* Hv = reinterpret_cast<const float4*>(H);

    for (int base = 0; base < deg; base += 32) {
        int nchunk = min(32, deg - base);
        int idx = 0;
        float pval = 1.0f;
        if (lane < nchunk) {
            idx = csr[start + base + lane];
            if (MODE == 0) pval = pre[idx];
        }
        #pragma unroll 4
        for (int j = 0; j < nchunk; ++j) {
            int s = __shfl_sync(0xffffffffu, idx, j);
            float p = (MODE == 0) ? __shfl_sync(0xffffffffu, pval, j) : 1.0f;
            if (lane < F4) {
                float4 v = Hv[(size_t)s * F4 + lane];
                if (MODE == 0) {
                    acc.x = fmaf(v.x, p, acc.x);
                    acc.y = fmaf(v.y, p, acc.y);
                    acc.z = fmaf(v.z, p, acc.z);
                    acc.w = fmaf(v.w, p, acc.w);
                } else {
                    acc.x += v.x; acc.y += v.y; acc.z += v.z; acc.w += v.w;
                }
            }
        }
    }

    if (lane < F4) {
        if (MODE >= 1) {
            float s = invin[w];
            float4 b = reinterpret_cast<const float4*>(bias)[lane];
            acc.x = acc.x * s + b.x;
            acc.y = acc.y * s + b.y;
            acc.z = acc.z * s + b.z;
            acc.w = acc.w * s + b.w;
        }
        if (MODE == 1) {
            float s2 = invout2[w];
            acc.x = fmaxf(acc.x, 0.f) * s2; acc.y = fmaxf(acc.y, 0.f) * s2;
            acc.z = fmaxf(acc.z, 0.f) * s2; acc.w = fmaxf(acc.w, 0.f) * s2;
        }
        if (MODE == 2) {
            reinterpret_cast<float4*>(outf)[(size_t)w * F4 + lane] = acc;
        } else {
            uint32_t h0, l0, h1, l1;
            split2(acc.x, acc.y, h0, l0);
            split2(acc.z, acc.w, h1, l1);
            size_t base2 = (size_t)w * (F4 * 4) + lane * 4;
            *reinterpret_cast<uint2*>(outh + base2) = make_uint2(h0, h1);
            *reinterpret_cast<uint2*>(outl + base2) = make_uint2(l0, l1);
        }
    }
}

// ---------------- common mma helpers ----------------
__device__ __forceinline__ void mma16816(float* d, const uint32_t* a, uint32_t b0, uint32_t b1) {
    asm("mma.sync.aligned.m16n8k16.row.col.f32.bf16.bf16.f32 "
        "{%0,%1,%2,%3}, {%4,%5,%6,%7}, {%8,%9}, {%0,%1,%2,%3};"
        : "+f"(d[0]), "+f"(d[1]), "+f"(d[2]), "+f"(d[3])
        : "r"(a[0]), "r"(a[1]), "r"(a[2]), "r"(a[3]), "r"(b0), "r"(b1));
}

__device__ __forceinline__ void ldmat_x4(uint32_t* r, uint32_t saddr) {
    asm volatile("ldmatrix.sync.aligned.m8n8.x4.shared.b16 {%0,%1,%2,%3}, [%4];"
                 : "=r"(r[0]), "=r"(r[1]), "=r"(r[2]), "=r"(r[3]) : "r"(saddr));
}

__device__ __forceinline__ uint32_t smem_u32(const void* p) {
    uint32_t a;
    asm("{ .reg .u64 t; cvta.to.shared.u64 t, %1; cvt.u32.u64 %0, t; }" : "=r"(a) : "l"(p));
    return a;
}

__device__ __forceinline__ void cp16(uint32_t dst, const void* src, int sz) {
    asm volatile("cp.async.ca.shared.global [%0], [%1], 16, %2;"
                 :: "r"(dst), "l"(src), "r"(sz));
}

constexpr int MMA_LDS = 40;          // 80B rows -> conflict-free ldmatrix

// ============ big GEMM: 256x128 tile, 512 threads (16 warps), double buffer ============
constexpr int PB_A = 20480;
constexpr int PB_WOFF = 40960;
constexpr int PB_W = 10240;
constexpr int PB_BYTES = 61440;
constexpr int PB_SMEM = 2 * PB_BYTES;  // 122880

template <bool EPI1>
__global__ __launch_bounds__(512, 1)
void mgemm256_kernel(const __nv_bfloat16* __restrict__ Agh,
                     const __nv_bfloat16* __restrict__ Agl,
                     const __nv_bfloat16* __restrict__ Wth,
                     const __nv_bfloat16* __restrict__ Wtl,
                     float* __restrict__ Cf,
                     __nv_bfloat16* __restrict__ Ch, __nv_bfloat16* __restrict__ Cl,
                     int M, int N, int K,
                     const float* __restrict__ invin,
                     const float* __restrict__ bias,
                     const float* __restrict__ invout) {
    extern __shared__ __align__(16) char smem[];
    const uint32_t base = smem_u32(smem);

    const int tid = threadIdx.x;
    const int lane = tid & 31;
    const int wid = tid >> 5;             // 0..15
    const int m0 = blockIdx.x * 256;
    const int n0 = blockIdx.y * 128;
    const int wm = (wid & 7) * 32;        // 8 M-warps x 32 rows
    const int wn = (wid >> 3) * 64;       // 2 N-warps x 64 cols
    const int g = lane >> 2;
    const int tg2 = (lane & 3) * 2;

    const int arow = lane & 15;
    const int akoff = (lane >> 4) * 8;
    const int wrow = (lane & 7) + ((lane >> 4) << 3);
    const int wkoff = (lane & 8) ? 8 : 0;

    float acc[2][8][4] = {};   // 2 m-subtiles x 8 n-groups

    auto copy_chunk = [&](int kc, int b) {
        uint32_t bb = base + b * PB_BYTES;
        // A: 2048 cp16 over 512 threads = 4/thread
        #pragma unroll
        for (int it = 0; it < 4; ++it) {
            int idx = it * 512 + tid;
            bool lo = idx >= 1024;
            int idx2 = idx & 1023;
            int row = idx2 >> 2;
            int seg = idx2 & 3;
            int gr = m0 + row;
            int cr = min(gr, M - 1);
            const __nv_bfloat16* src = (lo ? Agl : Agh) + (size_t)cr * K + kc * 32 + seg * 8;
            uint32_t dst = bb + (lo ? PB_A : 0) + (uint32_t)(row * 80 + seg * 16);
            cp16(dst, src, (gr < M) ? 16 : 0);
        }
        // W: 1024 cp16 over 512 threads = 2/thread
        #pragma unroll
        for (int it = 0; it < 2; ++it) {
            int idx = it * 512 + tid;
            bool lo = idx >= 512;
            int idx2 = idx & 511;
            int row = idx2 >> 2;
            int seg = idx2 & 3;
            const __nv_bfloat16* src = (lo ? Wtl : Wth) + (size_t)(n0 + row) * K + kc * 32 + seg * 8;
            uint32_t dst = bb + PB_WOFF + (lo ? PB_W : 0) + (uint32_t)(row * 80 + seg * 16);
            cp16(dst, src, 16);
        }
        asm volatile("cp.async.commit_group;");
    };

    auto compute = [&](int b) {
        uint32_t bb = base + b * PB_BYTES;
        #pragma unroll
        for (int ks = 0; ks < 2; ++ks) {
            int kk = ks * 16;
            uint32_t ah[2][4], al[2][4];
            #pragma unroll
            for (int mi = 0; mi < 2; ++mi) {
                uint32_t aoff = bb + (uint32_t)(((wm + mi * 16 + arow) * MMA_LDS + kk + akoff) * 2);
                ldmat_x4(ah[mi], aoff);
                ldmat_x4(al[mi], aoff + PB_A);
            }
            #pragma unroll
            for (int nj = 0; nj < 4; ++nj) {
                uint32_t wh[4], wl[4];
                uint32_t woff = bb + PB_WOFF +
                    (uint32_t)(((wn + nj * 16 + wrow) * MMA_LDS + kk + wkoff) * 2);
                ldmat_x4(wh, woff);
                ldmat_x4(wl, woff + PB_W);
                #pragma unroll
                for (int q = 0; q < 2; ++q)
                    #pragma unroll
                    for (int mi = 0; mi < 2; ++mi)
                        mma16816(acc[mi][nj * 2 + q], ah[mi], wh[q * 2], wh[q * 2 + 1]);
                #pragma unroll
                for (int q = 0; q < 2; ++q)
                    #pragma unroll
                    for (int mi = 0; mi < 2; ++mi)
                        mma16816(acc[mi][nj * 2 + q], ah[mi], wl[q * 2], wl[q * 2 + 1]);
                #pragma unroll
                for (int q = 0; q < 2; ++q)
                    #pragma unroll
                    for (int mi = 0; mi < 2; ++mi)
                        mma16816(acc[mi][nj * 2 + q], al[mi], wh[q * 2], wh[q * 2 + 1]);
            }
        }
    };

    const int KC = K >> 5;
    copy_chunk(0, 0);
    for (int kc = 0; kc < KC; ++kc) {
        int b = kc & 1;
        if (kc + 1 < KC) {
            copy_chunk(kc + 1, 1 - b);
            asm volatile("cp.async.wait_group 1;");
        } else {
            asm volatile("cp.async.wait_group 0;");
        }
        __syncthreads();
        compute(b);
        __syncthreads();
    }

    // ---- epilogue ----
    #pragma unroll
    for (int mi = 0; mi < 2; ++mi) {
        int r0 = m0 + wm + mi * 16 + g;
        int r1 = r0 + 8;
        float i0 = 1.f, i1 = 1.f, o0 = 1.f, o1 = 1.f;
        if (EPI1) {
            if (r0 < M) { i0 = invin[r0]; o0 = invout[r0]; }
            if (r1 < M) { i1 = invin[r1]; o1 = invout[r1]; }
        }
        #pragma unroll
        for (int ni = 0; ni < 8; ++ni) {
            int col = n0 + wn + ni * 8 + tg2;
            if (EPI1) {
                float bx = bias[col], by = bias[col + 1];
                if (r0 < M) {
                    float vx = fmaxf(acc[mi][ni][0] * i0 + bx, 0.f) * o0;
                    float vy = fmaxf(acc[mi][ni][1] * i0 + by, 0.f) * o0;
                    uint32_t h, l;
                    split2(vx, vy, h, l);
                    *reinterpret_cast<uint32_t*>(Ch + (size_t)r0 * N + col) = h;
                    *reinterpret_cast<uint32_t*>(Cl + (size_t)r0 * N + col) = l;
                }
                if (r1 < M) {
                    float vx = fmaxf(acc[mi][ni][2] * i1 + bx, 0.f) * o1;
                    float vy = fmaxf(acc[mi][ni][3] * i1 + by, 0.f) * o1;
                    uint32_t h, l;
                    split2(vx, vy, h, l);
                    *reinterpret_cast<uint32_t*>(Ch + (size_t)r1 * N + col) = h;
                    *reinterpret_cast<uint32_t*>(Cl + (size_t)r1 * N + col) = l;
                }
            } else {
                if (r0 < M)
                    *reinterpret_cast<float2*>(Cf + (size_t)r0 * N + col) =
                        make_float2(acc[mi][ni][0], acc[mi][ni][1]);
                if (r1 < M)
                    *reinterpret_cast<float2*>(Cf + (size_t)r1 * N + col) =
                        make_float2(acc[mi][ni][2], acc[mi][ni][3]);
            }
        }
    }
}

// ============ small GEMM (GEMM3): 128x64 tile, 3 CTA/SM ============
template <int TNT, bool EPI1>
__global__ __launch_bounds__(256, (TNT == 64 ? 3 : 2))
void mgemm_kernel(const __nv_bfloat16* __restrict__ Agh,
                  const __nv_bfloat16* __restrict__ Agl,
                  const __nv_bfloat16* __restrict__ Wth,
                  const __nv_bfloat16* __restrict__ Wtl,
                  float* __restrict__ Cf,
                  __nv_bfloat16* __restrict__ Ch, __nv_bfloat16* __restrict__ Cl,
                  int M, int N, int K,
                  const float* __restrict__ invin,
                  const float* __restrict__ bias,
                  const float* __restrict__ invout) {
    constexpr int NI = TNT / 16;
    __shared__ __align__(16) __nv_bfloat16 Ah[128][MMA_LDS];
    __shared__ __align__(16) __nv_bfloat16 Al[128][MMA_LDS];
    __shared__ __align__(16) __nv_bfloat16 Wh[TNT][MMA_LDS];
    __shared__ __align__(16) __nv_bfloat16 Wl[TNT][MMA_LDS];

    const int tid = threadIdx.x;
    const int lane = tid & 31;
    const int wid = tid >> 5;
    const int m0 = blockIdx.x * 128;
    const int n0 = blockIdx.y * TNT;
    const int wm = (wid & 3) * 32;
    const int wn = (wid >> 2) * (TNT / 2);
    const int g = lane >> 2;
    const int tg2 = (lane & 3) * 2;

    const int arow = lane & 15;
    const int akoff = (lane >> 4) * 8;
    const int wrow = (lane & 7) + ((lane >> 4) << 3);
    const int wkoff = (lane & 8) ? 8 : 0;

    const uint32_t uAh = smem_u32(&Ah[0][0]);
    const uint32_t uAl = smem_u32(&Al[0][0]);
    const uint32_t uWh = smem_u32(&Wh[0][0]);
    const uint32_t uWl = smem_u32(&Wl[0][0]);

    float acc[2][NI][4] = {};
    const uint4 z4 = make_uint4(0u, 0u, 0u, 0u);

    for (int k0 = 0; k0 < K; k0 += 32) {
        if (k0 > 0) __syncthreads();
        #pragma unroll
        for (int it = 0; it < 4; ++it) {
            int idx = it * 256 + tid;
            bool lo = idx >= 512;
            int idx2 = idx & 511;
            int row = idx2 >> 2;
            int seg = idx2 & 3;
            int gr = m0 + row;
            const __nv_bfloat16* gsrc = (lo ? Agl : Agh) + (size_t)gr * K + k0 + seg * 8;
            uint4 v = (gr < M) ? *reinterpret_cast<const uint4*>(gsrc) : z4;
            __nv_bfloat16* sdst = (lo ? &Al[0][0] : &Ah[0][0]) + row * MMA_LDS + seg * 8;
            *reinterpret_cast<uint4*>(sdst) = v;
        }
        #pragma unroll
        for (int it = 0; it < TNT / 32; ++it) {
            int idx = it * 256 + tid;
            bool lo = idx >= TNT * 4;
            int idx2 = lo ? (idx - TNT * 4) : idx;
            int n = idx2 >> 2;
            int seg = idx2 & 3;
            int gn = n0 + n;
            uint4 v = z4;
            if (gn < N)
                v = *reinterpret_cast<const uint4*>((lo ? Wtl : Wth) + (size_t)gn * K + k0 + seg * 8);
            __nv_bfloat16* sdst = (lo ? &Wl[0][0] : &Wh[0][0]) + n * MMA_LDS + seg * 8;
            *reinterpret_cast<uint4*>(sdst) = v;
        }
        __syncthreads();

        #pragma unroll
        for (int ks = 0; ks < 2; ++ks) {
            int kk = ks * 16;
            uint32_t ah[2][4], al[2][4];
            #pragma unroll
            for (int mi = 0; mi < 2; ++mi) {
                uint32_t aoff = (uint32_t)(((wm + mi * 16 + arow) * MMA_LDS + kk + akoff) * 2);
                ldmat_x4(ah[mi], uAh + aoff);
                ldmat_x4(al[mi], uAl + aoff);
            }
            #pragma unroll
            for (int nj = 0; nj < NI / 2; ++nj) {
                uint32_t wh[4], wl[4];
                uint32_t woff = (uint32_t)(((wn + nj * 16 + wrow) * MMA_LDS + kk + wkoff) * 2);
                ldmat_x4(wh, uWh + woff);
                ldmat_x4(wl, uWl + woff);
                #pragma unroll
                for (int q = 0; q < 2; ++q)
                    #pragma unroll
                    for (int mi = 0; mi < 2; ++mi)
                        mma16816(acc[mi][nj * 2 + q], ah[mi], wh[q * 2], wh[q * 2 + 1]);
                #pragma unroll
                for (int q = 0; q < 2; ++q)
                    #pragma unroll
                    for (int mi = 0; mi < 2; ++mi)
                        mma16816(acc[mi][nj * 2 + q], ah[mi], wl[q * 2], wl[q * 2 + 1]);
                #pragma unroll
                for (int q = 0; q < 2; ++q)
                    #pragma unroll
                    for (int mi = 0; mi < 2; ++mi)
                        mma16816(acc[mi][nj * 2 + q], al[mi], wh[q * 2], wh[q * 2 + 1]);
            }
        }
    }

    #pragma unroll
    for (int mi = 0; mi < 2; ++mi) {
        int r0 = m0 + wm + mi * 16 + g;
        int r1 = r0 + 8;
        #pragma unroll
        for (int ni = 0; ni < NI; ++ni) {
            int col = n0 + wn + ni * 8 + tg2;
            if (col >= N) continue;
            if (r0 < M)
                *reinterpret_cast<float2*>(Cf + (size_t)r0 * N + col) =
                    make_float2(acc[mi][ni][0], acc[mi][ni][1]);
            if (r1 < M)
                *reinterpret_cast<float2*>(Cf + (size_t)r1 * N + col) =
                    make_float2(acc[mi][ni][2], acc[mi][ni][3]);
        }
    }
}

// ---------------- launch ----------------
static inline int cdiv(int a, int b) { return (a + b - 1) / b; }

extern "C" void kernel_launch(void* const* d_in, const int* in_sizes, int n_in,
                              void* d_out, int out_size) {
    const float* feat = (const float*)d_in[0];
    const int*   src  = (const int*)d_in[1];
    const int*   dst  = (const int*)d_in[2];
    const float* W1   = (const float*)d_in[3];
    const float* b1   = (const float*)d_in[4];
    const float* W2   = (const float*)d_in[5];
    const float* b2   = (const float*)d_in[6];
    const float* W3   = (const float*)d_in[7];
    const float* b3   = (const float*)d_in[8];
    const int E = in_sizes[1];
    float* out = (float*)d_out;

    float *T2, *T3, *invout, *invin;
    int *idegi, *rowstart, *csr;
    __nv_bfloat16 *a1h, *a1l, *x1h, *x1l, *x2h, *x2l;
    __nv_bfloat16 *wt1h, *wt1l, *wt2h, *wt2l, *wt3h, *wt3l;
    cudaGetSymbolAddress((void**)&a1h, g_A1h);
    cudaGetSymbolAddress((void**)&a1l, g_A1l);
    cudaGetSymbolAddress((void**)&x1h, g_X1h);
    cudaGetSymbolAddress((void**)&x1l, g_X1l);
    cudaGetSymbolAddress((void**)&x2h, g_X2h);
    cudaGetSymbolAddress((void**)&x2l, g_X2l);
    cudaGetSymbolAddress((void**)&T2, g_T2);
    cudaGetSymbolAddress((void**)&T3, g_T3);
    cudaGetSymbolAddress((void**)&invout, g_invout);
    cudaGetSymbolAddress((void**)&invin, g_invin);
    cudaGetSymbolAddress((void**)&idegi, g_idegi);
    cudaGetSymbolAddress((void**)&rowstart, g_rowstart);
    cudaGetSymbolAddress((void**)&csr, g_csr);
    cudaGetSymbolAddress((void**)&wt1h, g_Wt1h);
    cudaGetSymbolAddress((void**)&wt1l, g_Wt1l);
    cudaGetSymbolAddress((void**)&wt2h, g_Wt2h);
    cudaGetSymbolAddress((void**)&wt2l, g_Wt2l);
    cudaGetSymbolAddress((void**)&wt3h, g_Wt3h);
    cudaGetSymbolAddress((void**)&wt3l, g_Wt3l);

    const int T = 256;
    const int MG256 = cdiv(NN, 256);
    const int MG128 = cdiv(NN, 128);
    const int AGG_GRID = cdiv(NN, 8);

    cudaFuncSetAttribute(mgemm256_kernel<true>,
                         cudaFuncAttributeMaxDynamicSharedMemorySize, PB_SMEM);
    cudaFuncSetAttribute(mgemm256_kernel<false>,
                         cudaFuncAttributeMaxDynamicSharedMemorySize, PB_SMEM);

    build_kernel<<<NBLD, TBLD>>>(src, dst, E, W1, W2, W3);

    // ---- Layer 1 ----
    agg_kernel<32, 0><<<AGG_GRID, T>>>(feat, csr, rowstart, idegi, invout,
                                       nullptr, nullptr, nullptr,
                                       nullptr, a1h, a1l, NN);
    {
        dim3 grid(MG256, 2);
        mgemm256_kernel<true><<<grid, 512, PB_SMEM>>>(a1h, a1l, wt1h, wt1l,
                                                      nullptr, x1h, x1l,
                                                      NN, 256, 128, invin, b1, invout);
    }

    // ---- Layer 2 ----
    {
        dim3 grid(MG256, 1);
        mgemm256_kernel<false><<<grid, 512, PB_SMEM>>>(x1h, x1l, wt2h, wt2l,
                                                       T2, nullptr, nullptr,
                                                       NN, 128, 256, nullptr, nullptr, nullptr);
    }
    agg_kernel<32, 1><<<AGG_GRID, T>>>(T2, csr, rowstart, idegi, nullptr,
                                       invin, b2, invout,
                                       nullptr, x2h, x2l, NN);

    // ---- Layer 3 ----
    {
        dim3 grid(MG128, 1);
        mgemm_kernel<64, false><<<grid, T>>>(x2h, x2l, wt3h, wt3l,
                                             T3, nullptr, nullptr,
                                             NN, 40, 128, nullptr, nullptr, nullptr);
    }
    agg_kernel<10, 2><<<AGG_GRID, T>>>(T3, csr, rowstart, idegi, nullptr,
                                       invin, b3, nullptr,
                                       out, nullptr, nullptr, NN);
}

// round 15
// speedup vs baseline: 1.0357x; 1.0357x over previous
#include <cuda_runtime.h>
#include <cuda_bf16.h>
#include <cuda_fp16.h>
#include <cstdint>
#include <cstddef>

#define NN 100000
#define EDGES_MAX 800000
#define NBLD 148
#define TBLD 1024
#define NPB ((NN + NBLD - 1) / NBLD)

// ---------------- scratch (static __device__, no allocation) ----------------
__device__ __align__(256) __nv_bfloat16 g_A1h[(size_t)NN * 128];
__device__ __align__(256) __nv_bfloat16 g_A1l[(size_t)NN * 128];
__device__ __align__(256) __nv_bfloat16 g_X1h[(size_t)NN * 256];
__device__ __align__(256) __nv_bfloat16 g_X1l[(size_t)NN * 256];
__device__ __align__(256) __nv_bfloat16 g_X2h[(size_t)NN * 128];
__device__ __align__(256) __nv_bfloat16 g_X2l[(size_t)NN * 128];
__device__ __align__(256) __half g_feat16[(size_t)NN * 128];  // feat * invout, fp16
__device__ __align__(256) __half g_T2h[(size_t)NN * 128];
__device__ __align__(256) __half g_T3h[(size_t)NN * 40];
__device__ __align__(256) float g_invout[NN];
__device__ __align__(256) float g_invin[NN];
__device__ __align__(256) int g_odegi[NN];
__device__ __align__(256) int g_idegi[NN];
__device__ __align__(256) int g_rowstart[NN];
__device__ __align__(256) int g_ctr[NN];
__device__ __align__(256) int g_blocksum[NBLD];
__device__ __align__(256) int g_csr[EDGES_MAX];
__device__ unsigned g_barC;
__device__ __align__(256) __nv_bfloat16 g_Wt1h[256 * 128];
__device__ __align__(256) __nv_bfloat16 g_Wt1l[256 * 128];
__device__ __align__(256) __nv_bfloat16 g_Wt2h[128 * 256];
__device__ __align__(256) __nv_bfloat16 g_Wt2l[128 * 256];
__device__ __align__(256) __nv_bfloat16 g_Wt3h[40 * 128];
__device__ __align__(256) __nv_bfloat16 g_Wt3l[40 * 128];

__device__ __forceinline__ uint32_t pack_bf2(float x, float y) {
    __nv_bfloat162 t = __floats2bfloat162_rn(x, y);
    return *reinterpret_cast<uint32_t*>(&t);
}
__device__ __forceinline__ void split2(float x, float y, uint32_t& hi, uint32_t& lo) {
    __nv_bfloat162 h = __floats2bfloat162_rn(x, y);
    float rx = x - __bfloat162float(h.x);
    float ry = y - __bfloat162float(h.y);
    hi = *reinterpret_cast<uint32_t*>(&h);
    lo = pack_bf2(rx, ry);
}
__device__ __forceinline__ uint32_t pack_h2(float x, float y) {
    __half2 t = __floats2half2_rn(x, y);
    return *reinterpret_cast<uint32_t*>(&t);
}

// ---------------- fused build kernel ----------------
__device__ __forceinline__ void grid_bar() {
    __syncthreads();
    __threadfence();
    if (threadIdx.x == 0) {
        unsigned old = atomicAdd(&g_barC, 1u);
        unsigned target = (old / NBLD + 1u) * NBLD;
        while (*(volatile unsigned*)&g_barC < target) { __nanosleep(64); }
    }
    __syncthreads();
}

__device__ __forceinline__ void wsplit_one(const float* __restrict__ W, int K, int N, int i,
                                           __nv_bfloat16* __restrict__ th,
                                           __nv_bfloat16* __restrict__ tl) {
    int k = i / N, n = i % N;
    float w = W[i];
    __nv_bfloat16 h = __float2bfloat16(w);
    float r = w - __bfloat162float(h);
    th[n * K + k] = h;
    tl[n * K + k] = __float2bfloat16(r);
}

__global__ __launch_bounds__(TBLD, 1)
void build_kernel(const int* __restrict__ src, const int* __restrict__ dst, int E,
                  const float* __restrict__ W1, const float* __restrict__ W2,
                  const float* __restrict__ W3, const float* __restrict__ feat) {
    __shared__ int sm_scan[TBLD];
    __shared__ int sm_bs[NBLD];

    const int t = threadIdx.x;
    const int b = blockIdx.x;
    const int gi = b * TBLD + t;

    if (gi < NN) { g_odegi[gi] = 0; g_idegi[gi] = 0; }
    if (gi < 128 * 256) {
        wsplit_one(W1, 128, 256, gi, g_Wt1h, g_Wt1l);
        wsplit_one(W2, 256, 128, gi, g_Wt2h, g_Wt2l);
    }
    if (gi < 128 * 40) wsplit_one(W3, 128, 40, gi, g_Wt3h, g_Wt3l);
    grid_bar();

    for (int e = gi; e < E; e += NBLD * TBLD) {
        atomicAdd(&g_odegi[src[e]], 1);
        atomicAdd(&g_idegi[dst[e]], 1);
    }
    grid_bar();

    const int node = b * NPB + t;
    const int deg = (t < NPB && node < NN) ? g_idegi[node] : 0;
    sm_scan[t] = deg;
    __syncthreads();
    #pragma unroll
    for (int off = 1; off < TBLD; off <<= 1) {
        int a = (t >= off) ? sm_scan[t - off] : 0;
        __syncthreads();
        sm_scan[t] += a;
        __syncthreads();
    }
    const int incl = sm_scan[t];
    if (t == 0) g_blocksum[b] = sm_scan[TBLD - 1];
    grid_bar();

    if (t < NBLD) sm_bs[t] = g_blocksum[t];
    __syncthreads();
    int off = 0;
    for (int j = 0; j < b; ++j) off += sm_bs[j];
    if (t < NPB && node < NN) {
        int rs = off + incl - deg;
        g_rowstart[node] = rs;
        g_ctr[node] = rs;
        g_invout[node] = rsqrtf(fmaxf((float)g_odegi[node], 1.0f));
        g_invin[node]  = rsqrtf(fmaxf((float)deg, 1.0f));
    }
    grid_bar();

    // phase e: CSR fill + feat -> fp16 prescaled by invout
    for (int e = gi; e < E; e += NBLD * TBLD) {
        int p = atomicAdd(&g_ctr[dst[e]], 1);
        g_csr[p] = src[e];
    }
    for (int i = gi; i < NN * 32; i += NBLD * TBLD) {   // float4 groups
        int nd = i >> 5;
        float s = g_invout[nd];
        float4 f = reinterpret_cast<const float4*>(feat)[i];
        uint2 v = make_uint2(pack_h2(f.x * s, f.y * s), pack_h2(f.z * s, f.w * s));
        reinterpret_cast<uint2*>(g_feat16)[i] = v;
    }
}

// ---------------- fp16 gather aggregation, 128-wide: 2 edges/iter ----------------
// MODE 0: plain sum -> split-bf16 out                                  (agg1)
// MODE 1: v = relu(sum*invin + bias)*invout2 -> split-bf16             (agg2)
template <int MODE>
__global__ __launch_bounds__(256)
void agg128h_kernel(const __half* __restrict__ H, const int* __restrict__ csr,
                    const int* __restrict__ rowstart, const int* __restrict__ degi,
                    const float* __restrict__ invin, const float* __restrict__ bias,
                    const float* __restrict__ invout2,
                    __nv_bfloat16* __restrict__ outh, __nv_bfloat16* __restrict__ outl,
                    int n) {
    int w = (blockIdx.x * blockDim.x + threadIdx.x) >> 5;
    if (w >= n) return;
    int lane = threadIdx.x & 31;
    int half_id = lane >> 4;       // 0/1: which edge of the pair
    int c8 = lane & 15;            // 8-col chunk
    int start = rowstart[w];
    int deg = degi[w];

    float acc[8] = {};

    for (int e2 = 0; e2 < deg; e2 += 2) {
        int eidx = e2 + half_id;
        if (eidx < deg) {
            int s = csr[start + eidx];
            uint4 v = *reinterpret_cast<const uint4*>(H + (size_t)s * 128 + c8 * 8);
            const __half2* h2 = reinterpret_cast<const __half2*>(&v);
            #pragma unroll
            for (int j = 0; j < 4; ++j) {
                float2 f = __half22float2(h2[j]);
                acc[j * 2] += f.x;
                acc[j * 2 + 1] += f.y;
            }
        }
    }
    #pragma unroll
    for (int j = 0; j < 8; ++j)
        acc[j] += __shfl_xor_sync(0xffffffffu, acc[j], 16);

    if (lane < 16) {
        if (MODE == 1) {
            float s = invin[w];
            float o = invout2[w];
            float4 b0 = *reinterpret_cast<const float4*>(bias + c8 * 8);
            float4 b1 = *reinterpret_cast<const float4*>(bias + c8 * 8 + 4);
            acc[0] = fmaxf(acc[0] * s + b0.x, 0.f) * o;
            acc[1] = fmaxf(acc[1] * s + b0.y, 0.f) * o;
            acc[2] = fmaxf(acc[2] * s + b0.z, 0.f) * o;
            acc[3] = fmaxf(acc[3] * s + b0.w, 0.f) * o;
            acc[4] = fmaxf(acc[4] * s + b1.x, 0.f) * o;
            acc[5] = fmaxf(acc[5] * s + b1.y, 0.f) * o;
            acc[6] = fmaxf(acc[6] * s + b1.z, 0.f) * o;
            acc[7] = fmaxf(acc[7] * s + b1.w, 0.f) * o;
        }
        uint4 hv, lv;
        split2(acc[0], acc[1], hv.x, lv.x);
        split2(acc[2], acc[3], hv.y, lv.y);
        split2(acc[4], acc[5], hv.z, lv.z);
        split2(acc[6], acc[7], hv.w, lv.w);
        size_t off = (size_t)w * 128 + c8 * 8;
        *reinterpret_cast<uint4*>(outh + off) = hv;
        *reinterpret_cast<uint4*>(outl + off) = lv;
    }
}

// ---------------- fp16 gather, 40-wide: 3 edges/iter, fp32 out (final) ----------------
__global__ __launch_bounds__(256)
void agg40h_kernel(const __half* __restrict__ H, const int* __restrict__ csr,
                   const int* __restrict__ rowstart, const int* __restrict__ degi,
                   const float* __restrict__ invin, const float* __restrict__ bias,
                   float* __restrict__ out, int n) {
    int w = (blockIdx.x * blockDim.x + threadIdx.x) >> 5;
    if (w >= n) return;
    int lane = threadIdx.x & 31;
    int grp = lane / 10;           // 0,1,2 (3 -> idle lanes 30,31)
    int c4 = lane - grp * 10;      // 4-col chunk 0..9
    int start = rowstart[w];
    int deg = degi[w];

    float acc[4] = {};

    for (int e3 = 0; e3 < deg; e3 += 3) {
        int eidx = e3 + grp;
        if (grp < 3 && eidx < deg) {
            int s = csr[start + eidx];
            uint2 v = *reinterpret_cast<const uint2*>(H + (size_t)s * 40 + c4 * 4);
            __half2 h0 = *reinterpret_cast<__half2*>(&v.x);
            __half2 h1 = *reinterpret_cast<__half2*>(&v.y);
            float2 f0 = __half22float2(h0);
            float2 f1 = __half22float2(h1);
            acc[0] += f0.x; acc[1] += f0.y; acc[2] += f1.x; acc[3] += f1.y;
        }
    }
    // FIXED reduction: shuffle the SNAPSHOT so no lane's partial is double-counted.
    // Only lanes < 10 (grp 0) consume the result; lane+10 / lane+20 < 32 for them.
    #pragma unroll
    for (int j = 0; j < 4; ++j) {
        float orig = acc[j];
        float t1 = __shfl_sync(0xffffffffu, orig, (lane + 10) & 31);
        float t2 = __shfl_sync(0xffffffffu, orig, (lane + 20) & 31);
        acc[j] = orig + t1 + t2;
    }
    if (lane < 10) {
        float s = invin[w];
        float4 b = *reinterpret_cast<const float4*>(bias + c4 * 4);
        float4 v;
        v.x = acc[0] * s + b.x;
        v.y = acc[1] * s + b.y;
        v.z = acc[2] * s + b.z;
        v.w = acc[3] * s + b.w;
        *reinterpret_cast<float4*>(out + (size_t)w * 40 + c4 * 4) = v;
    }
}

// ---------------- common mma helpers ----------------
__device__ __forceinline__ void mma16816(float* d, const uint32_t* a, uint32_t b0, uint32_t b1) {
    asm("mma.sync.aligned.m16n8k16.row.col.f32.bf16.bf16.f32 "
        "{%0,%1,%2,%3}, {%4,%5,%6,%7}, {%8,%9}, {%0,%1,%2,%3};"
        : "+f"(d[0]), "+f"(d[1]), "+f"(d[2]), "+f"(d[3])
        : "r"(a[0]), "r"(a[1]), "r"(a[2]), "r"(a[3]), "r"(b0), "r"(b1));
}

__device__ __forceinline__ void ldmat_x4(uint32_t* r, uint32_t saddr) {
    asm volatile("ldmatrix.sync.aligned.m8n8.x4.shared.b16 {%0,%1,%2,%3}, [%4];"
                 : "=r"(r[0]), "=r"(r[1]), "=r"(r[2]), "=r"(r[3]) : "r"(saddr));
}

__device__ __forceinline__ uint32_t smem_u32(const void* p) {
    uint32_t a;
    asm("{ .reg .u64 t; cvta.to.shared.u64 t, %1; cvt.u32.u64 %0, t; }" : "=r"(a) : "l"(p));
    return a;
}

__device__ __forceinline__ void cp16(uint32_t dst, const void* src, int sz) {
    asm volatile("cp.async.ca.shared.global [%0], [%1], 16, %2;"
                 :: "r"(dst), "l"(src), "r"(sz));
}

constexpr int MMA_LDS = 40;

// ============ big GEMM: 256x128 tile, 512 threads, double buffer ============
constexpr int PB_A = 20480;
constexpr int PB_WOFF = 40960;
constexpr int PB_W = 10240;
constexpr int PB_BYTES = 61440;
constexpr int PB_SMEM = 2 * PB_BYTES;

// EPI1: split-bf16 out (Ch/Cl) with relu(acc*invin+bias)*invout; else half out (ChF)
template <bool EPI1>
__global__ __launch_bounds__(512, 1)
void mgemm256_kernel(const __nv_bfloat16* __restrict__ Agh,
                     const __nv_bfloat16* __restrict__ Agl,
                     const __nv_bfloat16* __restrict__ Wth,
                     const __nv_bfloat16* __restrict__ Wtl,
                     __half* __restrict__ ChF,
                     __nv_bfloat16* __restrict__ Ch, __nv_bfloat16* __restrict__ Cl,
                     int M, int N, int K,
                     const float* __restrict__ invin,
                     const float* __restrict__ bias,
                     const float* __restrict__ invout) {
    extern __shared__ __align__(16) char smem[];
    const uint32_t base = smem_u32(smem);

    const int tid = threadIdx.x;
    const int lane = tid & 31;
    const int wid = tid >> 5;
    const int m0 = blockIdx.x * 256;
    const int n0 = blockIdx.y * 128;
    const int wm = (wid & 7) * 32;
    const int wn = (wid >> 3) * 64;
    const int g = lane >> 2;
    const int tg2 = (lane & 3) * 2;

    const int arow = lane & 15;
    const int akoff = (lane >> 4) * 8;
    const int wrow = (lane & 7) + ((lane >> 4) << 3);
    const int wkoff = (lane & 8) ? 8 : 0;

    float acc[2][8][4] = {};

    auto copy_chunk = [&](int kc, int b) {
        uint32_t bb = base + b * PB_BYTES;
        #pragma unroll
        for (int it = 0; it < 4; ++it) {
            int idx = it * 512 + tid;
            bool lo = idx >= 1024;
            int idx2 = idx & 1023;
            int row = idx2 >> 2;
            int seg = idx2 & 3;
            int gr = m0 + row;
            int cr = min(gr, M - 1);
            const __nv_bfloat16* src = (lo ? Agl : Agh) + (size_t)cr * K + kc * 32 + seg * 8;
            uint32_t dst = bb + (lo ? PB_A : 0) + (uint32_t)(row * 80 + seg * 16);
            cp16(dst, src, (gr < M) ? 16 : 0);
        }
        #pragma unroll
        for (int it = 0; it < 2; ++it) {
            int idx = it * 512 + tid;
            bool lo = idx >= 512;
            int idx2 = idx & 511;
            int row = idx2 >> 2;
            int seg = idx2 & 3;
            const __nv_bfloat16* src = (lo ? Wtl : Wth) + (size_t)(n0 + row) * K + kc * 32 + seg * 8;
            uint32_t dst = bb + PB_WOFF + (lo ? PB_W : 0) + (uint32_t)(row * 80 + seg * 16);
            cp16(dst, src, 16);
        }
        asm volatile("cp.async.commit_group;");
    };

    auto compute = [&](int b) {
        uint32_t bb = base + b * PB_BYTES;
        #pragma unroll
        for (int ks = 0; ks < 2; ++ks) {
            int kk = ks * 16;
            uint32_t ah[2][4], al[2][4];
            #pragma unroll
            for (int mi = 0; mi < 2; ++mi) {
                uint32_t aoff = bb + (uint32_t)(((wm + mi * 16 + arow) * MMA_LDS + kk + akoff) * 2);
                ldmat_x4(ah[mi], aoff);
                ldmat_x4(al[mi], aoff + PB_A);
            }
            #pragma unroll
            for (int nj = 0; nj < 4; ++nj) {
                uint32_t wh[4], wl[4];
                uint32_t woff = bb + PB_WOFF +
                    (uint32_t)(((wn + nj * 16 + wrow) * MMA_LDS + kk + wkoff) * 2);
                ldmat_x4(wh, woff);
                ldmat_x4(wl, woff + PB_W);
                #pragma unroll
                for (int q = 0; q < 2; ++q)
                    #pragma unroll
                    for (int mi = 0; mi < 2; ++mi)
                        mma16816(acc[mi][nj * 2 + q], ah[mi], wh[q * 2], wh[q * 2 + 1]);
                #pragma unroll
                for (int q = 0; q < 2; ++q)
                    #pragma unroll
                    for (int mi = 0; mi < 2; ++mi)
                        mma16816(acc[mi][nj * 2 + q], ah[mi], wl[q * 2], wl[q * 2 + 1]);
                #pragma unroll
                for (int q = 0; q < 2; ++q)
                    #pragma unroll
                    for (int mi = 0; mi < 2; ++mi)
                        mma16816(acc[mi][nj * 2 + q], al[mi], wh[q * 2], wh[q * 2 + 1]);
            }
        }
    };

    const int KC = K >> 5;
    copy_chunk(0, 0);
    for (int kc = 0; kc < KC; ++kc) {
        int b = kc & 1;
        if (kc + 1 < KC) {
            copy_chunk(kc + 1, 1 - b);
            asm volatile("cp.async.wait_group 1;");
        } else {
            asm volatile("cp.async.wait_group 0;");
        }
        __syncthreads();
        compute(b);
        __syncthreads();
    }

    #pragma unroll
    for (int mi = 0; mi < 2; ++mi) {
        int r0 = m0 + wm + mi * 16 + g;
        int r1 = r0 + 8;
        float i0 = 1.f, i1 = 1.f, o0 = 1.f, o1 = 1.f;
        if (EPI1) {
            if (r0 < M) { i0 = invin[r0]; o0 = invout[r0]; }
            if (r1 < M) { i1 = invin[r1]; o1 = invout[r1]; }
        }
        #pragma unroll
        for (int ni = 0; ni < 8; ++ni) {
            int col = n0 + wn + ni * 8 + tg2;
            if (EPI1) {
                float bx = bias[col], by = bias[col + 1];
                if (r0 < M) {
                    float vx = fmaxf(acc[mi][ni][0] * i0 + bx, 0.f) * o0;
                    float vy = fmaxf(acc[mi][ni][1] * i0 + by, 0.f) * o0;
                    uint32_t h, l;
                    split2(vx, vy, h, l);
                    *reinterpret_cast<uint32_t*>(Ch + (size_t)r0 * N + col) = h;
                    *reinterpret_cast<uint32_t*>(Cl + (size_t)r0 * N + col) = l;
                }
                if (r1 < M) {
                    float vx = fmaxf(acc[mi][ni][2] * i1 + bx, 0.f) * o1;
                    float vy = fmaxf(acc[mi][ni][3] * i1 + by, 0.f) * o1;
                    uint32_t h, l;
                    split2(vx, vy, h, l);
                    *reinterpret_cast<uint32_t*>(Ch + (size_t)r1 * N + col) = h;
                    *reinterpret_cast<uint32_t*>(Cl + (size_t)r1 * N + col) = l;
                }
            } else {
                if (r0 < M)
                    *reinterpret_cast<uint32_t*>(ChF + (size_t)r0 * N + col) =
                        pack_h2(acc[mi][ni][0], acc[mi][ni][1]);
                if (r1 < M)
                    *reinterpret_cast<uint32_t*>(ChF + (size_t)r1 * N + col) =
                        pack_h2(acc[mi][ni][2], acc[mi][ni][3]);
            }
        }
    }
}

// ============ small GEMM (GEMM3): 128x64 tile, 3 CTA/SM, half out ============
__global__ __launch_bounds__(256, 3)
void mgemm_small_kernel(const __nv_bfloat16* __restrict__ Agh,
                        const __nv_bfloat16* __restrict__ Agl,
                        const __nv_bfloat16* __restrict__ Wth,
                        const __nv_bfloat16* __restrict__ Wtl,
                        __half* __restrict__ ChF,
                        int M, int N, int K) {
    constexpr int TNT = 64;
    constexpr int NI = 4;
    __shared__ __align__(16) __nv_bfloat16 Ah[128][MMA_LDS];
    __shared__ __align__(16) __nv_bfloat16 Al[128][MMA_LDS];
    __shared__ __align__(16) __nv_bfloat16 Wh[TNT][MMA_LDS];
    __shared__ __align__(16) __nv_bfloat16 Wl[TNT][MMA_LDS];

    const int tid = threadIdx.x;
    const int lane = tid & 31;
    const int wid = tid >> 5;
    const int m0 = blockIdx.x * 128;
    const int n0 = blockIdx.y * TNT;
    const int wm = (wid & 3) * 32;
    const int wn = (wid >> 2) * (TNT / 2);
    const int g = lane >> 2;
    const int tg2 = (lane & 3) * 2;

    const int arow = lane & 15;
    const int akoff = (lane >> 4) * 8;
    const int wrow = (lane & 7) + ((lane >> 4) << 3);
    const int wkoff = (lane & 8) ? 8 : 0;

    const uint32_t uAh = smem_u32(&Ah[0][0]);
    const uint32_t uAl = smem_u32(&Al[0][0]);
    const uint32_t uWh = smem_u32(&Wh[0][0]);
    const uint32_t uWl = smem_u32(&Wl[0][0]);

    float acc[2][NI][4] = {};
    const uint4 z4 = make_uint4(0u, 0u, 0u, 0u);

    for (int k0 = 0; k0 < K; k0 += 32) {
        if (k0 > 0) __syncthreads();
        #pragma unroll
        for (int it = 0; it < 4; ++it) {
            int idx = it * 256 + tid;
            bool lo = idx >= 512;
            int idx2 = idx & 511;
            int row = idx2 >> 2;
            int seg = idx2 & 3;
            int gr = m0 + row;
            const __nv_bfloat16* gsrc = (lo ? Agl : Agh) + (size_t)gr * K + k0 + seg * 8;
            uint4 v = (gr < M) ? *reinterpret_cast<const uint4*>(gsrc) : z4;
            __nv_bfloat16* sdst = (lo ? &Al[0][0] : &Ah[0][0]) + row * MMA_LDS + seg * 8;
            *reinterpret_cast<uint4*>(sdst) = v;
        }
        #pragma unroll
        for (int it = 0; it < 2; ++it) {
            int idx = it * 256 + tid;
            bool lo = idx >= 256;
            int idx2 = lo ? (idx - 256) : idx;
            int n = idx2 >> 2;
            int seg = idx2 & 3;
            int gn = n0 + n;
            uint4 v = z4;
            if (gn < N)
                v = *reinterpret_cast<const uint4*>((lo ? Wtl : Wth) + (size_t)gn * K + k0 + seg * 8);
            __nv_bfloat16* sdst = (lo ? &Wl[0][0] : &Wh[0][0]) + n * MMA_LDS + seg * 8;
            *reinterpret_cast<uint4*>(sdst) = v;
        }
        __syncthreads();

        #pragma unroll
        for (int ks = 0; ks < 2; ++ks) {
            int kk = ks * 16;
            uint32_t ah[2][4], al[2][4];
            #pragma unroll
            for (int mi = 0; mi < 2; ++mi) {
                uint32_t aoff = (uint32_t)(((wm + mi * 16 + arow) * MMA_LDS + kk + akoff) * 2);
                ldmat_x4(ah[mi], uAh + aoff);
                ldmat_x4(al[mi], uAl + aoff);
            }
            #pragma unroll
            for (int nj = 0; nj < NI / 2; ++nj) {
                uint32_t wh[4], wl[4];
                uint32_t woff = (uint32_t)(((wn + nj * 16 + wrow) * MMA_LDS + kk + wkoff) * 2);
                ldmat_x4(wh, uWh + woff);
                ldmat_x4(wl, uWl + woff);
                #pragma unroll
                for (int q = 0; q < 2; ++q)
                    #pragma unroll
                    for (int mi = 0; mi < 2; ++mi)
                        mma16816(acc[mi][nj * 2 + q], ah[mi], wh[q * 2], wh[q * 2 + 1]);
                #pragma unroll
                for (int q = 0; q < 2; ++q)
                    #pragma unroll
                    for (int mi = 0; mi < 2; ++mi)
                        mma16816(acc[mi][nj * 2 + q], ah[mi], wl[q * 2], wl[q * 2 + 1]);
                #pragma unroll
                for (int q = 0; q < 2; ++q)
                    #pragma unroll
                    for (int mi = 0; mi < 2; ++mi)
                        mma16816(acc[mi][nj * 2 + q], al[mi], wh[q * 2], wh[q * 2 + 1]);
            }
        }
    }

    #pragma unroll
    for (int mi = 0; mi < 2; ++mi) {
        int r0 = m0 + wm + mi * 16 + g;
        int r1 = r0 + 8;
        #pragma unroll
        for (int ni = 0; ni < NI; ++ni) {
            int col = n0 + wn + ni * 8 + tg2;
            if (col >= N) continue;
            if (r0 < M)
                *reinterpret_cast<uint32_t*>(ChF + (size_t)r0 * N + col) =
                    pack_h2(acc[mi][ni][0], acc[mi][ni][1]);
            if (r1 < M)
                *reinterpret_cast<uint32_t*>(ChF + (size_t)r1 * N + col) =
                    pack_h2(acc[mi][ni][2], acc[mi][ni][3]);
        }
    }
}

// ---------------- launch ----------------
static inline int cdiv(int a, int b) { return (a + b - 1) / b; }

extern "C" void kernel_launch(void* const* d_in, const int* in_sizes, int n_in,
                              void* d_out, int out_size) {
    const float* feat = (const float*)d_in[0];
    const int*   src  = (const int*)d_in[1];
    const int*   dst  = (const int*)d_in[2];
    const float* W1   = (const float*)d_in[3];
    const float* b1   = (const float*)d_in[4];
    const float* W2   = (const float*)d_in[5];
    const float* b2   = (const float*)d_in[6];
    const float* W3   = (const float*)d_in[7];
    const float* b3   = (const float*)d_in[8];
    const int E = in_sizes[1];
    float* out = (float*)d_out;

    float *invout, *invin;
    int *idegi, *rowstart, *csr;
    __half *feat16, *t2h, *t3h;
    __nv_bfloat16 *a1h, *a1l, *x1h, *x1l, *x2h, *x2l;
    __nv_bfloat16 *wt1h, *wt1l, *wt2h, *wt2l, *wt3h, *wt3l;
    cudaGetSymbolAddress((void**)&a1h, g_A1h);
    cudaGetSymbolAddress((void**)&a1l, g_A1l);
    cudaGetSymbolAddress((void**)&x1h, g_X1h);
    cudaGetSymbolAddress((void**)&x1l, g_X1l);
    cudaGetSymbolAddress((void**)&x2h, g_X2h);
    cudaGetSymbolAddress((void**)&x2l, g_X2l);
    cudaGetSymbolAddress((void**)&feat16, g_feat16);
    cudaGetSymbolAddress((void**)&t2h, g_T2h);
    cudaGetSymbolAddress((void**)&t3h, g_T3h);
    cudaGetSymbolAddress((void**)&invout, g_invout);
    cudaGetSymbolAddress((void**)&invin, g_invin);
    cudaGetSymbolAddress((void**)&idegi, g_idegi);
    cudaGetSymbolAddress((void**)&rowstart, g_rowstart);
    cudaGetSymbolAddress((void**)&csr, g_csr);
    cudaGetSymbolAddress((void**)&wt1h, g_Wt1h);
    cudaGetSymbolAddress((void**)&wt1l, g_Wt1l);
    cudaGetSymbolAddress((void**)&wt2h, g_Wt2h);
    cudaGetSymbolAddress((void**)&wt2l, g_Wt2l);
    cudaGetSymbolAddress((void**)&wt3h, g_Wt3h);
    cudaGetSymbolAddress((void**)&wt3l, g_Wt3l);

    const int T = 256;
    const int MG256 = cdiv(NN, 256);
    const int MG128 = cdiv(NN, 128);
    const int AGG_GRID = cdiv(NN, 8);

    cudaFuncSetAttribute(mgemm256_kernel<true>,
                         cudaFuncAttributeMaxDynamicSharedMemorySize, PB_SMEM);
    cudaFuncSetAttribute(mgemm256_kernel<false>,
                         cudaFuncAttributeMaxDynamicSharedMemorySize, PB_SMEM);

    // build: degrees + scan + CSR + weight split + inv norms + feat->fp16 prescale
    build_kernel<<<NBLD, TBLD>>>(src, dst, E, W1, W2, W3, feat);

    // ---- Layer 1 ----
    agg128h_kernel<0><<<AGG_GRID, T>>>(feat16, csr, rowstart, idegi,
                                       nullptr, nullptr, nullptr, a1h, a1l, NN);
    {
        dim3 grid(MG256, 2);
        mgemm256_kernel<true><<<grid, 512, PB_SMEM>>>(a1h, a1l, wt1h, wt1l,
                                                      nullptr, x1h, x1l,
                                                      NN, 256, 128, invin, b1, invout);
    }

    // ---- Layer 2 ----
    {
        dim3 grid(MG256, 1);
        mgemm256_kernel<false><<<grid, 512, PB_SMEM>>>(x1h, x1l, wt2h, wt2l,
                                                       t2h, nullptr, nullptr,
                                                       NN, 128, 256, nullptr, nullptr, nullptr);
    }
    agg128h_kernel<1><<<AGG_GRID, T>>>(t2h, csr, rowstart, idegi,
                                       invin, b2, invout, x2h, x2l, NN);

    // ---- Layer 3 ----
    {
        dim3 grid(MG128, 1);
        mgemm_small_kernel<<<grid, T>>>(x2h, x2l, wt3h, wt3l, t3h, NN, 40, 128);
    }
    agg40h_kernel<<<AGG_GRID, T>>>(t3h, csr, rowstart, idegi, invin, b3, out, NN);
}

// round 16
// speedup vs baseline: 1.3444x; 1.2980x over previous
#include <cuda_runtime.h>
#include <cuda_fp16.h>
#include <cstdint>
#include <cstddef>

#define NN 100000
#define EDGES_MAX 800000
#define NBLD 148
#define TBLD 1024
#define NPB ((NN + NBLD - 1) / NBLD)

// ---------------- scratch (static __device__, no allocation) ----------------
__device__ __align__(256) __half g_A1[(size_t)NN * 128];      // agg1 out, fp16
__device__ __align__(256) __half g_X1[(size_t)NN * 256];      // layer1 act, fp16
__device__ __align__(256) __half g_X2[(size_t)NN * 128];      // layer2 act, fp16
__device__ __align__(256) __half g_feat16[(size_t)NN * 128];  // feat * invout, fp16
__device__ __align__(256) __half g_T2h[(size_t)NN * 128];
__device__ __align__(256) __half g_T3h[(size_t)NN * 40];
__device__ __align__(256) float g_invout[NN];
__device__ __align__(256) float g_invin[NN];
__device__ __align__(256) int g_odegi[NN];
__device__ __align__(256) int g_idegi[NN];
__device__ __align__(256) int g_rowstart[NN];
__device__ __align__(256) int g_ctr[NN];
__device__ __align__(256) int g_blocksum[NBLD];
__device__ __align__(256) int g_csr[EDGES_MAX];
__device__ unsigned g_barC;
// W^T split-fp16 (hi/lo), layout [N][K] K-contiguous
__device__ __align__(256) __half g_Wt1h[256 * 128];
__device__ __align__(256) __half g_Wt1l[256 * 128];
__device__ __align__(256) __half g_Wt2h[128 * 256];
__device__ __align__(256) __half g_Wt2l[128 * 256];
__device__ __align__(256) __half g_Wt3h[40 * 128];
__device__ __align__(256) __half g_Wt3l[40 * 128];

__device__ __forceinline__ uint32_t pack_h2(float x, float y) {
    __half2 t = __floats2half2_rn(x, y);
    return *reinterpret_cast<uint32_t*>(&t);
}

// ---------------- fused build kernel ----------------
__device__ __forceinline__ void grid_bar() {
    __syncthreads();
    __threadfence();
    if (threadIdx.x == 0) {
        unsigned old = atomicAdd(&g_barC, 1u);
        unsigned target = (old / NBLD + 1u) * NBLD;
        while (*(volatile unsigned*)&g_barC < target) { __nanosleep(64); }
    }
    __syncthreads();
}

__device__ __forceinline__ void wsplit_one(const float* __restrict__ W, int K, int N, int i,
                                           __half* __restrict__ th,
                                           __half* __restrict__ tl) {
    int k = i / N, n = i % N;
    float w = W[i];
    __half h = __float2half_rn(w);
    float r = w - __half2float(h);
    th[n * K + k] = h;
    tl[n * K + k] = __float2half_rn(r);
}

__global__ __launch_bounds__(TBLD, 1)
void build_kernel(const int* __restrict__ src, const int* __restrict__ dst, int E,
                  const float* __restrict__ W1, const float* __restrict__ W2,
                  const float* __restrict__ W3, const float* __restrict__ feat) {
    __shared__ int sm_scan[TBLD];
    __shared__ int sm_bs[NBLD];

    const int t = threadIdx.x;
    const int b = blockIdx.x;
    const int gi = b * TBLD + t;

    if (gi < NN) { g_odegi[gi] = 0; g_idegi[gi] = 0; }
    if (gi < 128 * 256) {
        wsplit_one(W1, 128, 256, gi, g_Wt1h, g_Wt1l);
        wsplit_one(W2, 256, 128, gi, g_Wt2h, g_Wt2l);
    }
    if (gi < 128 * 40) wsplit_one(W3, 128, 40, gi, g_Wt3h, g_Wt3l);
    grid_bar();

    for (int e = gi; e < E; e += NBLD * TBLD) {
        atomicAdd(&g_odegi[src[e]], 1);
        atomicAdd(&g_idegi[dst[e]], 1);
    }
    grid_bar();

    const int node = b * NPB + t;
    const int deg = (t < NPB && node < NN) ? g_idegi[node] : 0;
    sm_scan[t] = deg;
    __syncthreads();
    #pragma unroll
    for (int off = 1; off < TBLD; off <<= 1) {
        int a = (t >= off) ? sm_scan[t - off] : 0;
        __syncthreads();
        sm_scan[t] += a;
        __syncthreads();
    }
    const int incl = sm_scan[t];
    if (t == 0) g_blocksum[b] = sm_scan[TBLD - 1];
    grid_bar();

    if (t < NBLD) sm_bs[t] = g_blocksum[t];
    __syncthreads();
    int off = 0;
    for (int j = 0; j < b; ++j) off += sm_bs[j];
    if (t < NPB && node < NN) {
        int rs = off + incl - deg;
        g_rowstart[node] = rs;
        g_ctr[node] = rs;
        g_invout[node] = rsqrtf(fmaxf((float)g_odegi[node], 1.0f));
        g_invin[node]  = rsqrtf(fmaxf((float)deg, 1.0f));
    }
    grid_bar();

    // phase e: CSR fill + feat -> fp16 prescaled by invout
    for (int e = gi; e < E; e += NBLD * TBLD) {
        int p = atomicAdd(&g_ctr[dst[e]], 1);
        g_csr[p] = src[e];
    }
    for (int i = gi; i < NN * 32; i += NBLD * TBLD) {   // float4 groups
        int nd = i >> 5;
        float s = g_invout[nd];
        float4 f = reinterpret_cast<const float4*>(feat)[i];
        uint2 v = make_uint2(pack_h2(f.x * s, f.y * s), pack_h2(f.z * s, f.w * s));
        reinterpret_cast<uint2*>(g_feat16)[i] = v;
    }
}

// ---------------- fp16 gather aggregation, 128-wide: 2 edges/iter ----------------
// MODE 0: plain sum -> fp16 out                                        (agg1)
// MODE 1: v = relu(sum*invin + bias)*invout2 -> fp16                   (agg2)
template <int MODE>
__global__ __launch_bounds__(256)
void agg128h_kernel(const __half* __restrict__ H, const int* __restrict__ csr,
                    const int* __restrict__ rowstart, const int* __restrict__ degi,
                    const float* __restrict__ invin, const float* __restrict__ bias,
                    const float* __restrict__ invout2,
                    __half* __restrict__ outh, int n) {
    int w = (blockIdx.x * blockDim.x + threadIdx.x) >> 5;
    if (w >= n) return;
    int lane = threadIdx.x & 31;
    int half_id = lane >> 4;
    int c8 = lane & 15;
    int start = rowstart[w];
    int deg = degi[w];

    float acc[8] = {};

    for (int e2 = 0; e2 < deg; e2 += 2) {
        int eidx = e2 + half_id;
        if (eidx < deg) {
            int s = csr[start + eidx];
            uint4 v = *reinterpret_cast<const uint4*>(H + (size_t)s * 128 + c8 * 8);
            const __half2* h2 = reinterpret_cast<const __half2*>(&v);
            #pragma unroll
            for (int j = 0; j < 4; ++j) {
                float2 f = __half22float2(h2[j]);
                acc[j * 2] += f.x;
                acc[j * 2 + 1] += f.y;
            }
        }
    }
    #pragma unroll
    for (int j = 0; j < 8; ++j)
        acc[j] += __shfl_xor_sync(0xffffffffu, acc[j], 16);

    if (lane < 16) {
        if (MODE == 1) {
            float s = invin[w];
            float o = invout2[w];
            float4 b0 = *reinterpret_cast<const float4*>(bias + c8 * 8);
            float4 b1 = *reinterpret_cast<const float4*>(bias + c8 * 8 + 4);
            acc[0] = fmaxf(acc[0] * s + b0.x, 0.f) * o;
            acc[1] = fmaxf(acc[1] * s + b0.y, 0.f) * o;
            acc[2] = fmaxf(acc[2] * s + b0.z, 0.f) * o;
            acc[3] = fmaxf(acc[3] * s + b0.w, 0.f) * o;
            acc[4] = fmaxf(acc[4] * s + b1.x, 0.f) * o;
            acc[5] = fmaxf(acc[5] * s + b1.y, 0.f) * o;
            acc[6] = fmaxf(acc[6] * s + b1.z, 0.f) * o;
            acc[7] = fmaxf(acc[7] * s + b1.w, 0.f) * o;
        }
        uint4 hv;
        hv.x = pack_h2(acc[0], acc[1]);
        hv.y = pack_h2(acc[2], acc[3]);
        hv.z = pack_h2(acc[4], acc[5]);
        hv.w = pack_h2(acc[6], acc[7]);
        *reinterpret_cast<uint4*>(outh + (size_t)w * 128 + c8 * 8) = hv;
    }
}

// ---------------- fp16 gather, 40-wide: 3 edges/iter, fp32 out (final) ----------------
__global__ __launch_bounds__(256)
void agg40h_kernel(const __half* __restrict__ H, const int* __restrict__ csr,
                   const int* __restrict__ rowstart, const int* __restrict__ degi,
                   const float* __restrict__ invin, const float* __restrict__ bias,
                   float* __restrict__ out, int n) {
    int w = (blockIdx.x * blockDim.x + threadIdx.x) >> 5;
    if (w >= n) return;
    int lane = threadIdx.x & 31;
    int grp = lane / 10;
    int c4 = lane - grp * 10;
    int start = rowstart[w];
    int deg = degi[w];

    float acc[4] = {};

    for (int e3 = 0; e3 < deg; e3 += 3) {
        int eidx = e3 + grp;
        if (grp < 3 && eidx < deg) {
            int s = csr[start + eidx];
            uint2 v = *reinterpret_cast<const uint2*>(H + (size_t)s * 40 + c4 * 4);
            __half2 h0 = *reinterpret_cast<__half2*>(&v.x);
            __half2 h1 = *reinterpret_cast<__half2*>(&v.y);
            float2 f0 = __half22float2(h0);
            float2 f1 = __half22float2(h1);
            acc[0] += f0.x; acc[1] += f0.y; acc[2] += f1.x; acc[3] += f1.y;
        }
    }
    // reduction over groups via snapshot shuffles (valid for consuming lanes < 10)
    #pragma unroll
    for (int j = 0; j < 4; ++j) {
        float orig = acc[j];
        float t1 = __shfl_sync(0xffffffffu, orig, (lane + 10) & 31);
        float t2 = __shfl_sync(0xffffffffu, orig, (lane + 20) & 31);
        acc[j] = orig + t1 + t2;
    }
    if (lane < 10) {
        float s = invin[w];
        float4 b = *reinterpret_cast<const float4*>(bias + c4 * 4);
        float4 v;
        v.x = acc[0] * s + b.x;
        v.y = acc[1] * s + b.y;
        v.z = acc[2] * s + b.z;
        v.w = acc[3] * s + b.w;
        *reinterpret_cast<float4*>(out + (size_t)w * 40 + c4 * 4) = v;
    }
}

// ---------------- common mma helpers ----------------
__device__ __forceinline__ void mma16816h(float* d, const uint32_t* a, uint32_t b0, uint32_t b1) {
    asm("mma.sync.aligned.m16n8k16.row.col.f32.f16.f16.f32 "
        "{%0,%1,%2,%3}, {%4,%5,%6,%7}, {%8,%9}, {%0,%1,%2,%3};"
        : "+f"(d[0]), "+f"(d[1]), "+f"(d[2]), "+f"(d[3])
        : "r"(a[0]), "r"(a[1]), "r"(a[2]), "r"(a[3]), "r"(b0), "r"(b1));
}

__device__ __forceinline__ void ldmat_x4(uint32_t* r, uint32_t saddr) {
    asm volatile("ldmatrix.sync.aligned.m8n8.x4.shared.b16 {%0,%1,%2,%3}, [%4];"
                 : "=r"(r[0]), "=r"(r[1]), "=r"(r[2]), "=r"(r[3]) : "r"(saddr));
}

__device__ __forceinline__ uint32_t smem_u32(const void* p) {
    uint32_t a;
    asm("{ .reg .u64 t; cvta.to.shared.u64 t, %1; cvt.u32.u64 %0, t; }" : "=r"(a) : "l"(p));
    return a;
}

__device__ __forceinline__ void cp16(uint32_t dst, const void* src, int sz) {
    asm volatile("cp.async.ca.shared.global [%0], [%1], 16, %2;"
                 :: "r"(dst), "l"(src), "r"(sz));
}

constexpr int MMA_LDS = 40;          // 80B rows -> conflict-free ldmatrix

// ============ big GEMM: 256x128 tile, 512 threads, fp16 A + split-fp16 W, 2 passes ============
// per-stage layout: A(20480) Wh(10240) Wl(10240) = 40960 B; double buffered
constexpr int PB_WOFF = 20480;
constexpr int PB_W = 10240;
constexpr int PB_BYTES = 40960;
constexpr int PB_SMEM = 2 * PB_BYTES;  // 81920

// EPI1: relu(acc*invin+bias)*invout -> fp16 out; else raw fp16 out
template <bool EPI1>
__global__ __launch_bounds__(512, 1)
void mgemm256_kernel(const __half* __restrict__ Ag,
                     const __half* __restrict__ Wth,
                     const __half* __restrict__ Wtl,
                     __half* __restrict__ Cout,
                     int M, int N, int K,
                     const float* __restrict__ invin,
                     const float* __restrict__ bias,
                     const float* __restrict__ invout) {
    extern __shared__ __align__(16) char smem[];
    const uint32_t base = smem_u32(smem);

    const int tid = threadIdx.x;
    const int lane = tid & 31;
    const int wid = tid >> 5;             // 0..15
    const int m0 = blockIdx.x * 256;
    const int n0 = blockIdx.y * 128;
    const int wm = (wid & 7) * 32;        // 8 M-warps
    const int wn = (wid >> 3) * 64;       // 2 N-warps
    const int g = lane >> 2;
    const int tg2 = (lane & 3) * 2;

    const int arow = lane & 15;
    const int akoff = (lane >> 4) * 8;
    const int wrow = (lane & 7) + ((lane >> 4) << 3);
    const int wkoff = (lane & 8) ? 8 : 0;

    float acc[2][8][4] = {};

    auto copy_chunk = [&](int kc, int b) {
        uint32_t bb = base + b * PB_BYTES;
        // A: 256 rows x 4 segs = 1024 cp16 over 512 thr = 2/thread
        #pragma unroll
        for (int it = 0; it < 2; ++it) {
            int idx = it * 512 + tid;
            int row = idx >> 2;
            int seg = idx & 3;
            int gr = m0 + row;
            int cr = min(gr, M - 1);
            const __half* src = Ag + (size_t)cr * K + kc * 32 + seg * 8;
            uint32_t dst = bb + (uint32_t)(row * 80 + seg * 16);
            cp16(dst, src, (gr < M) ? 16 : 0);
        }
        // W: 128 rows x (hi,lo) x 4 segs = 1024 cp16 = 2/thread
        #pragma unroll
        for (int it = 0; it < 2; ++it) {
            int idx = it * 512 + tid;
            bool lo = idx >= 512;
            int idx2 = idx & 511;
            int row = idx2 >> 2;
            int seg = idx2 & 3;
            const __half* src = (lo ? Wtl : Wth) + (size_t)(n0 + row) * K + kc * 32 + seg * 8;
            uint32_t dst = bb + PB_WOFF + (lo ? PB_W : 0) + (uint32_t)(row * 80 + seg * 16);
            cp16(dst, src, 16);
        }
        asm volatile("cp.async.commit_group;");
    };

    auto compute = [&](int b) {
        uint32_t bb = base + b * PB_BYTES;
        #pragma unroll
        for (int ks = 0; ks < 2; ++ks) {
            int kk = ks * 16;
            uint32_t a[2][4];
            #pragma unroll
            for (int mi = 0; mi < 2; ++mi) {
                uint32_t aoff = bb + (uint32_t)(((wm + mi * 16 + arow) * MMA_LDS + kk + akoff) * 2);
                ldmat_x4(a[mi], aoff);
            }
            #pragma unroll
            for (int nj = 0; nj < 4; ++nj) {
                uint32_t wh[4], wl[4];
                uint32_t woff = bb + PB_WOFF +
                    (uint32_t)(((wn + nj * 16 + wrow) * MMA_LDS + kk + wkoff) * 2);
                ldmat_x4(wh, woff);
                ldmat_x4(wl, woff + PB_W);
                #pragma unroll
                for (int q = 0; q < 2; ++q)
                    #pragma unroll
                    for (int mi = 0; mi < 2; ++mi)
                        mma16816h(acc[mi][nj * 2 + q], a[mi], wh[q * 2], wh[q * 2 + 1]);
                #pragma unroll
                for (int q = 0; q < 2; ++q)
                    #pragma unroll
                    for (int mi = 0; mi < 2; ++mi)
                        mma16816h(acc[mi][nj * 2 + q], a[mi], wl[q * 2], wl[q * 2 + 1]);
            }
        }
    };

    const int KC = K >> 5;
    copy_chunk(0, 0);
    for (int kc = 0; kc < KC; ++kc) {
        int b = kc & 1;
        if (kc + 1 < KC) {
            copy_chunk(kc + 1, 1 - b);
            asm volatile("cp.async.wait_group 1;");
        } else {
            asm volatile("cp.async.wait_group 0;");
        }
        __syncthreads();
        compute(b);
        __syncthreads();
    }

    // ---- epilogue ----
    #pragma unroll
    for (int mi = 0; mi < 2; ++mi) {
        int r0 = m0 + wm + mi * 16 + g;
        int r1 = r0 + 8;
        float i0 = 1.f, i1 = 1.f, o0 = 1.f, o1 = 1.f;
        if (EPI1) {
            if (r0 < M) { i0 = invin[r0]; o0 = invout[r0]; }
            if (r1 < M) { i1 = invin[r1]; o1 = invout[r1]; }
        }
        #pragma unroll
        for (int ni = 0; ni < 8; ++ni) {
            int col = n0 + wn + ni * 8 + tg2;
            float vx0 = acc[mi][ni][0], vy0 = acc[mi][ni][1];
            float vx1 = acc[mi][ni][2], vy1 = acc[mi][ni][3];
            if (EPI1) {
                float bx = bias[col], by = bias[col + 1];
                vx0 = fmaxf(vx0 * i0 + bx, 0.f) * o0;
                vy0 = fmaxf(vy0 * i0 + by, 0.f) * o0;
                vx1 = fmaxf(vx1 * i1 + bx, 0.f) * o1;
                vy1 = fmaxf(vy1 * i1 + by, 0.f) * o1;
            }
            if (r0 < M)
                *reinterpret_cast<uint32_t*>(Cout + (size_t)r0 * N + col) = pack_h2(vx0, vy0);
            if (r1 < M)
                *reinterpret_cast<uint32_t*>(Cout + (size_t)r1 * N + col) = pack_h2(vx1, vy1);
        }
    }
}

// ============ small GEMM (GEMM3): 128x64 tile, 3 CTA/SM, fp16 2-pass ============
__global__ __launch_bounds__(256, 3)
void mgemm_small_kernel(const __half* __restrict__ Ag,
                        const __half* __restrict__ Wth,
                        const __half* __restrict__ Wtl,
                        __half* __restrict__ Cout,
                        int M, int N, int K) {
    constexpr int TNT = 64;
    constexpr int NI = 4;
    __shared__ __align__(16) __half As[128][MMA_LDS];
    __shared__ __align__(16) __half Wh[TNT][MMA_LDS];
    __shared__ __align__(16) __half Wl[TNT][MMA_LDS];

    const int tid = threadIdx.x;
    const int lane = tid & 31;
    const int wid = tid >> 5;
    const int m0 = blockIdx.x * 128;
    const int n0 = blockIdx.y * TNT;
    const int wm = (wid & 3) * 32;
    const int wn = (wid >> 2) * (TNT / 2);
    const int g = lane >> 2;
    const int tg2 = (lane & 3) * 2;

    const int arow = lane & 15;
    const int akoff = (lane >> 4) * 8;
    const int wrow = (lane & 7) + ((lane >> 4) << 3);
    const int wkoff = (lane & 8) ? 8 : 0;

    const uint32_t uA = smem_u32(&As[0][0]);
    const uint32_t uWh = smem_u32(&Wh[0][0]);
    const uint32_t uWl = smem_u32(&Wl[0][0]);

    float acc[2][NI][4] = {};
    const uint4 z4 = make_uint4(0u, 0u, 0u, 0u);

    for (int k0 = 0; k0 < K; k0 += 32) {
        if (k0 > 0) __syncthreads();
        // A: 128 rows x 4 segs = 512 uint4 over 256 thr = 2/thread
        #pragma unroll
        for (int it = 0; it < 2; ++it) {
            int idx = it * 256 + tid;
            int row = idx >> 2;
            int seg = idx & 3;
            int gr = m0 + row;
            uint4 v = (gr < M)
                ? *reinterpret_cast<const uint4*>(Ag + (size_t)gr * K + k0 + seg * 8) : z4;
            *reinterpret_cast<uint4*>(&As[0][0] + row * MMA_LDS + seg * 8) = v;
        }
        // W: 64 rows x (hi,lo) x 4 segs = 512 = 2/thread
        #pragma unroll
        for (int it = 0; it < 2; ++it) {
            int idx = it * 256 + tid;
            bool lo = idx >= 256;
            int idx2 = idx & 255;
            int n = idx2 >> 2;
            int seg = idx2 & 3;
            int gn = n0 + n;
            uint4 v = z4;
            if (gn < N)
                v = *reinterpret_cast<const uint4*>((lo ? Wtl : Wth) + (size_t)gn * K + k0 + seg * 8);
            __half* sdst = (lo ? &Wl[0][0] : &Wh[0][0]) + n * MMA_LDS + seg * 8;
            *reinterpret_cast<uint4*>(sdst) = v;
        }
        __syncthreads();

        #pragma unroll
        for (int ks = 0; ks < 2; ++ks) {
            int kk = ks * 16;
            uint32_t a[2][4];
            #pragma unroll
            for (int mi = 0; mi < 2; ++mi) {
                uint32_t aoff = uA + (uint32_t)(((wm + mi * 16 + arow) * MMA_LDS + kk + akoff) * 2);
                ldmat_x4(a[mi], aoff);
            }
            #pragma unroll
            for (int nj = 0; nj < NI / 2; ++nj) {
                uint32_t wh[4], wl[4];
                uint32_t woff = (uint32_t)(((wn + nj * 16 + wrow) * MMA_LDS + kk + wkoff) * 2);
                ldmat_x4(wh, uWh + woff);
                ldmat_x4(wl, uWl + woff);
                #pragma unroll
                for (int q = 0; q < 2; ++q)
                    #pragma unroll
                    for (int mi = 0; mi < 2; ++mi)
                        mma16816h(acc[mi][nj * 2 + q], a[mi], wh[q * 2], wh[q * 2 + 1]);
                #pragma unroll
                for (int q = 0; q < 2; ++q)
                    #pragma unroll
                    for (int mi = 0; mi < 2; ++mi)
                        mma16816h(acc[mi][nj * 2 + q], a[mi], wl[q * 2], wl[q * 2 + 1]);
            }
        }
    }

    #pragma unroll
    for (int mi = 0; mi < 2; ++mi) {
        int r0 = m0 + wm + mi * 16 + g;
        int r1 = r0 + 8;
        #pragma unroll
        for (int ni = 0; ni < NI; ++ni) {
            int col = n0 + wn + ni * 8 + tg2;
            if (col >= N) continue;
            if (r0 < M)
                *reinterpret_cast<uint32_t*>(Cout + (size_t)r0 * N + col) =
                    pack_h2(acc[mi][ni][0], acc[mi][ni][1]);
            if (r1 < M)
                *reinterpret_cast<uint32_t*>(Cout + (size_t)r1 * N + col) =
                    pack_h2(acc[mi][ni][2], acc[mi][ni][3]);
        }
    }
}

// ---------------- launch ----------------
static inline int cdiv(int a, int b) { return (a + b - 1) / b; }

extern "C" void kernel_launch(void* const* d_in, const int* in_sizes, int n_in,
                              void* d_out, int out_size) {
    const float* feat = (const float*)d_in[0];
    const int*   src  = (const int*)d_in[1];
    const int*   dst  = (const int*)d_in[2];
    const float* W1   = (const float*)d_in[3];
    const float* b1   = (const float*)d_in[4];
    const float* W2   = (const float*)d_in[5];
    const float* b2   = (const float*)d_in[6];
    const float* W3   = (const float*)d_in[7];
    const float* b3   = (const float*)d_in[8];
    const int E = in_sizes[1];
    float* out = (float*)d_out;

    float *invout, *invin;
    int *idegi, *rowstart, *csr;
    __half *a1, *x1, *x2, *feat16, *t2h, *t3h;
    __half *wt1h, *wt1l, *wt2h, *wt2l, *wt3h, *wt3l;
    cudaGetSymbolAddress((void**)&a1, g_A1);
    cudaGetSymbolAddress((void**)&x1, g_X1);
    cudaGetSymbolAddress((void**)&x2, g_X2);
    cudaGetSymbolAddress((void**)&feat16, g_feat16);
    cudaGetSymbolAddress((void**)&t2h, g_T2h);
    cudaGetSymbolAddress((void**)&t3h, g_T3h);
    cudaGetSymbolAddress((void**)&invout, g_invout);
    cudaGetSymbolAddress((void**)&invin, g_invin);
    cudaGetSymbolAddress((void**)&idegi, g_idegi);
    cudaGetSymbolAddress((void**)&rowstart, g_rowstart);
    cudaGetSymbolAddress((void**)&csr, g_csr);
    cudaGetSymbolAddress((void**)&wt1h, g_Wt1h);
    cudaGetSymbolAddress((void**)&wt1l, g_Wt1l);
    cudaGetSymbolAddress((void**)&wt2h, g_Wt2h);
    cudaGetSymbolAddress((void**)&wt2l, g_Wt2l);
    cudaGetSymbolAddress((void**)&wt3h, g_Wt3h);
    cudaGetSymbolAddress((void**)&wt3l, g_Wt3l);

    const int T = 256;
    const int MG256 = cdiv(NN, 256);
    const int MG128 = cdiv(NN, 128);
    const int AGG_GRID = cdiv(NN, 8);

    cudaFuncSetAttribute(mgemm256_kernel<true>,
                         cudaFuncAttributeMaxDynamicSharedMemorySize, PB_SMEM);
    cudaFuncSetAttribute(mgemm256_kernel<false>,
                         cudaFuncAttributeMaxDynamicSharedMemorySize, PB_SMEM);

    // build: degrees + scan + CSR + weight split + inv norms + feat->fp16 prescale
    build_kernel<<<NBLD, TBLD>>>(src, dst, E, W1, W2, W3, feat);

    // ---- Layer 1 ----
    agg128h_kernel<0><<<AGG_GRID, T>>>(feat16, csr, rowstart, idegi,
                                       nullptr, nullptr, nullptr, a1, NN);
    {
        dim3 grid(MG256, 2);
        mgemm256_kernel<true><<<grid, 512, PB_SMEM>>>(a1, wt1h, wt1l, x1,
                                                      NN, 256, 128, invin, b1, invout);
    }

    // ---- Layer 2 ----
    {
        dim3 grid(MG256, 1);
        mgemm256_kernel<false><<<grid, 512, PB_SMEM>>>(x1, wt2h, wt2l, t2h,
                                                       NN, 128, 256, nullptr, nullptr, nullptr);
    }
    agg128h_kernel<1><<<AGG_GRID, T>>>(t2h, csr, rowstart, idegi,
                                       invin, b2, invout, x2, NN);

    // ---- Layer 3 ----
    {
        dim3 grid(MG128, 1);
        mgemm_small_kernel<<<grid, T>>>(x2, wt3h, wt3l, t3h, NN, 40, 128);
    }
    agg40h_kernel<<<AGG_GRID, T>>>(t3h, csr, rowstart, idegi, invin, b3, out, NN);
}

// round 17
// speedup vs baseline: 1.5001x; 1.1158x over previous
#include <cuda_runtime.h>
#include <cuda_fp16.h>
#include <cstdint>
#include <cstddef>

#define NN 100000
#define EDGES_MAX 800000
#define NBLD 148
#define TBLD 1024
#define NPB ((NN + NBLD - 1) / NBLD)

// ---------------- scratch (static __device__, no allocation) ----------------
__device__ __align__(256) __half g_A1[(size_t)NN * 128];
__device__ __align__(256) __half g_X1[(size_t)NN * 256];
__device__ __align__(256) __half g_X2[(size_t)NN * 128];
__device__ __align__(256) __half g_feat16[(size_t)NN * 128];
__device__ __align__(256) __half g_T2h[(size_t)NN * 128];
__device__ __align__(256) __half g_T3h[(size_t)NN * 40];
__device__ __align__(256) float g_invout[NN];
__device__ __align__(256) float g_invin[NN];
__device__ __align__(256) int g_odegi[NN];
__device__ __align__(256) int g_idegi[NN];
__device__ __align__(256) int g_rowstart[NN];
__device__ __align__(256) int g_ctr[NN];
__device__ __align__(256) int g_blocksum[NBLD];
__device__ __align__(256) int g_csr[EDGES_MAX];
__device__ unsigned g_barC;
// W^T fp16, layout [N][K]
__device__ __align__(256) __half g_Wt1[256 * 128];
__device__ __align__(256) __half g_Wt2[128 * 256];
__device__ __align__(256) __half g_Wt3[40 * 128];

__device__ __forceinline__ uint32_t pack_h2(float x, float y) {
    __half2 t = __floats2half2_rn(x, y);
    return *reinterpret_cast<uint32_t*>(&t);
}

// ---------------- fused build kernel ----------------
__device__ __forceinline__ void grid_bar() {
    __syncthreads();
    __threadfence();
    if (threadIdx.x == 0) {
        unsigned old = atomicAdd(&g_barC, 1u);
        unsigned target = (old / NBLD + 1u) * NBLD;
        while (*(volatile unsigned*)&g_barC < target) { __nanosleep(64); }
    }
    __syncthreads();
}

__global__ __launch_bounds__(TBLD, 1)
void build_kernel(const int* __restrict__ src, const int* __restrict__ dst, int E,
                  const float* __restrict__ W1, const float* __restrict__ W2,
                  const float* __restrict__ W3, const float* __restrict__ feat) {
    __shared__ int sm_scan[TBLD];
    __shared__ int sm_bs[NBLD];

    const int t = threadIdx.x;
    const int b = blockIdx.x;
    const int gi = b * TBLD + t;

    if (gi < NN) { g_odegi[gi] = 0; g_idegi[gi] = 0; }
    if (gi < 128 * 256) {
        { int k = gi / 256, n = gi % 256; g_Wt1[n * 128 + k] = __float2half_rn(W1[gi]); }
        { int k = gi / 128, n = gi % 128; g_Wt2[n * 256 + k] = __float2half_rn(W2[gi]); }
    }
    if (gi < 128 * 40) {
        int k = gi / 40, n = gi % 40;
        g_Wt3[n * 128 + k] = __float2half_rn(W3[gi]);
    }
    grid_bar();

    for (int e = gi; e < E; e += NBLD * TBLD) {
        atomicAdd(&g_odegi[src[e]], 1);
        atomicAdd(&g_idegi[dst[e]], 1);
    }
    grid_bar();

    const int node = b * NPB + t;
    const int deg = (t < NPB && node < NN) ? g_idegi[node] : 0;
    sm_scan[t] = deg;
    __syncthreads();
    #pragma unroll
    for (int off = 1; off < TBLD; off <<= 1) {
        int a = (t >= off) ? sm_scan[t - off] : 0;
        __syncthreads();
        sm_scan[t] += a;
        __syncthreads();
    }
    const int incl = sm_scan[t];
    if (t == 0) g_blocksum[b] = sm_scan[TBLD - 1];
    grid_bar();

    if (t < NBLD) sm_bs[t] = g_blocksum[t];
    __syncthreads();
    int off = 0;
    for (int j = 0; j < b; ++j) off += sm_bs[j];
    if (t < NPB && node < NN) {
        int rs = off + incl - deg;
        g_rowstart[node] = rs;
        g_ctr[node] = rs;
        g_invout[node] = rsqrtf(fmaxf((float)g_odegi[node], 1.0f));
        g_invin[node]  = rsqrtf(fmaxf((float)deg, 1.0f));
    }
    grid_bar();

    // CSR fill + feat -> fp16 prescaled by invout
    for (int e = gi; e < E; e += NBLD * TBLD) {
        int p = atomicAdd(&g_ctr[dst[e]], 1);
        g_csr[p] = src[e];
    }
    for (int i = gi; i < NN * 32; i += NBLD * TBLD) {
        int nd = i >> 5;
        float s = g_invout[nd];
        float4 f = reinterpret_cast<const float4*>(feat)[i];
        uint2 v = make_uint2(pack_h2(f.x * s, f.y * s), pack_h2(f.z * s, f.w * s));
        reinterpret_cast<uint2*>(g_feat16)[i] = v;
    }
}

// ---------------- fp16 gather aggregation, 128-wide: 4 edges in flight ----------------
// MODE 0: plain sum -> fp16 out            (agg1)
// MODE 1: relu(sum*invin+bias)*invout2 -> fp16   (agg2)
template <int MODE>
__global__ __launch_bounds__(256)
void agg128h_kernel(const __half* __restrict__ H, const int* __restrict__ csr,
                    const int* __restrict__ rowstart, const int* __restrict__ degi,
                    const float* __restrict__ invin, const float* __restrict__ bias,
                    const float* __restrict__ invout2,
                    __half* __restrict__ outh, int n) {
    int w = (blockIdx.x * blockDim.x + threadIdx.x) >> 5;
    if (w >= n) return;
    int lane = threadIdx.x & 31;
    int half_id = lane >> 4;
    int c8 = lane & 15;
    int start = rowstart[w];
    int deg = degi[w];

    float acc[8] = {};

    for (int e2 = 0; e2 < deg; e2 += 4) {
        int ea = e2 + half_id;
        int eb = e2 + 2 + half_id;
        bool va = ea < deg, vb = eb < deg;
        int sa = 0, sb = 0;
        if (va) sa = csr[start + ea];
        if (vb) sb = csr[start + eb];
        uint4 v0 = make_uint4(0, 0, 0, 0), v1 = make_uint4(0, 0, 0, 0);
        if (va) v0 = *reinterpret_cast<const uint4*>(H + (size_t)sa * 128 + c8 * 8);
        if (vb) v1 = *reinterpret_cast<const uint4*>(H + (size_t)sb * 128 + c8 * 8);
        const __half2* h0 = reinterpret_cast<const __half2*>(&v0);
        const __half2* h1 = reinterpret_cast<const __half2*>(&v1);
        #pragma unroll
        for (int j = 0; j < 4; ++j) {
            float2 f0 = __half22float2(h0[j]);
            float2 f1 = __half22float2(h1[j]);
            acc[j * 2]     += f0.x + f1.x;
            acc[j * 2 + 1] += f0.y + f1.y;
        }
    }
    #pragma unroll
    for (int j = 0; j < 8; ++j)
        acc[j] += __shfl_xor_sync(0xffffffffu, acc[j], 16);

    if (lane < 16) {
        if (MODE == 1) {
            float s = invin[w];
            float o = invout2[w];
            float4 b0 = *reinterpret_cast<const float4*>(bias + c8 * 8);
            float4 b1 = *reinterpret_cast<const float4*>(bias + c8 * 8 + 4);
            acc[0] = fmaxf(acc[0] * s + b0.x, 0.f) * o;
            acc[1] = fmaxf(acc[1] * s + b0.y, 0.f) * o;
            acc[2] = fmaxf(acc[2] * s + b0.z, 0.f) * o;
            acc[3] = fmaxf(acc[3] * s + b0.w, 0.f) * o;
            acc[4] = fmaxf(acc[4] * s + b1.x, 0.f) * o;
            acc[5] = fmaxf(acc[5] * s + b1.y, 0.f) * o;
            acc[6] = fmaxf(acc[6] * s + b1.z, 0.f) * o;
            acc[7] = fmaxf(acc[7] * s + b1.w, 0.f) * o;
        }
        uint4 hv;
        hv.x = pack_h2(acc[0], acc[1]);
        hv.y = pack_h2(acc[2], acc[3]);
        hv.z = pack_h2(acc[4], acc[5]);
        hv.w = pack_h2(acc[6], acc[7]);
        *reinterpret_cast<uint4*>(outh + (size_t)w * 128 + c8 * 8) = hv;
    }
}

// ---------------- fp16 gather, 40-wide: 6 edges in flight, fp32 out ----------------
__global__ __launch_bounds__(256)
void agg40h_kernel(const __half* __restrict__ H, const int* __restrict__ csr,
                   const int* __restrict__ rowstart, const int* __restrict__ degi,
                   const float* __restrict__ invin, const float* __restrict__ bias,
                   float* __restrict__ out, int n) {
    int w = (blockIdx.x * blockDim.x + threadIdx.x) >> 5;
    if (w >= n) return;
    int lane = threadIdx.x & 31;
    int grp = lane / 10;
    int c4 = lane - grp * 10;
    int start = rowstart[w];
    int deg = degi[w];

    float acc[4] = {};

    for (int e3 = 0; e3 < deg; e3 += 6) {
        int ea = e3 + grp;
        int eb = e3 + 3 + grp;
        bool va = (grp < 3) && (ea < deg);
        bool vb = (grp < 3) && (eb < deg);
        int sa = 0, sb = 0;
        if (va) sa = csr[start + ea];
        if (vb) sb = csr[start + eb];
        uint2 v0 = make_uint2(0, 0), v1 = make_uint2(0, 0);
        if (va) v0 = *reinterpret_cast<const uint2*>(H + (size_t)sa * 40 + c4 * 4);
        if (vb) v1 = *reinterpret_cast<const uint2*>(H + (size_t)sb * 40 + c4 * 4);
        float2 f0 = __half22float2(*reinterpret_cast<__half2*>(&v0.x));
        float2 f1 = __half22float2(*reinterpret_cast<__half2*>(&v0.y));
        float2 f2 = __half22float2(*reinterpret_cast<__half2*>(&v1.x));
        float2 f3 = __half22float2(*reinterpret_cast<__half2*>(&v1.y));
        acc[0] += f0.x + f2.x;
        acc[1] += f0.y + f2.y;
        acc[2] += f1.x + f3.x;
        acc[3] += f1.y + f3.y;
    }
    // reduce over the 3 groups via snapshot shuffles (consumers: lanes < 10)
    #pragma unroll
    for (int j = 0; j < 4; ++j) {
        float orig = acc[j];
        float t1 = __shfl_sync(0xffffffffu, orig, (lane + 10) & 31);
        float t2 = __shfl_sync(0xffffffffu, orig, (lane + 20) & 31);
        acc[j] = orig + t1 + t2;
    }
    if (lane < 10) {
        float s = invin[w];
        float4 b = *reinterpret_cast<const float4*>(bias + c4 * 4);
        float4 v;
        v.x = acc[0] * s + b.x;
        v.y = acc[1] * s + b.y;
        v.z = acc[2] * s + b.z;
        v.w = acc[3] * s + b.w;
        *reinterpret_cast<float4*>(out + (size_t)w * 40 + c4 * 4) = v;
    }
}

// ---------------- common mma helpers ----------------
__device__ __forceinline__ void mma16816h(float* d, const uint32_t* a, uint32_t b0, uint32_t b1) {
    asm("mma.sync.aligned.m16n8k16.row.col.f32.f16.f16.f32 "
        "{%0,%1,%2,%3}, {%4,%5,%6,%7}, {%8,%9}, {%0,%1,%2,%3};"
        : "+f"(d[0]), "+f"(d[1]), "+f"(d[2]), "+f"(d[3])
        : "r"(a[0]), "r"(a[1]), "r"(a[2]), "r"(a[3]), "r"(b0), "r"(b1));
}

__device__ __forceinline__ void ldmat_x4(uint32_t* r, uint32_t saddr) {
    asm volatile("ldmatrix.sync.aligned.m8n8.x4.shared.b16 {%0,%1,%2,%3}, [%4];"
                 : "=r"(r[0]), "=r"(r[1]), "=r"(r[2]), "=r"(r[3]) : "r"(saddr));
}

__device__ __forceinline__ uint32_t smem_u32(const void* p) {
    uint32_t a;
    asm("{ .reg .u64 t; cvta.to.shared.u64 t, %1; cvt.u32.u64 %0, t; }" : "=r"(a) : "l"(p));
    return a;
}

__device__ __forceinline__ void cp16(uint32_t dst, const void* src, int sz) {
    asm volatile("cp.async.ca.shared.global [%0], [%1], 16, %2;"
                 :: "r"(dst), "l"(src), "r"(sz));
}

constexpr int MMA_LDS = 40;

// ============ big GEMM: 256x128 tile, 512 threads, fp16 A/W, 1 pass ============
// per-stage: A(20480) + W(10240) = 30720; double buffered
constexpr int PB_WOFF = 20480;
constexpr int PB_BYTES = 30720;
constexpr int PB_SMEM = 2 * PB_BYTES;  // 61440

template <bool EPI1>
__global__ __launch_bounds__(512, 1)
void mgemm256_kernel(const __half* __restrict__ Ag,
                     const __half* __restrict__ Wt,
                     __half* __restrict__ Cout,
                     int M, int N, int K,
                     const float* __restrict__ invin,
                     const float* __restrict__ bias,
                     const float* __restrict__ invout) {
    extern __shared__ __align__(16) char smem[];
    const uint32_t base = smem_u32(smem);

    const int tid = threadIdx.x;
    const int lane = tid & 31;
    const int wid = tid >> 5;
    const int m0 = blockIdx.x * 256;
    const int n0 = blockIdx.y * 128;
    const int wm = (wid & 7) * 32;
    const int wn = (wid >> 3) * 64;
    const int g = lane >> 2;
    const int tg2 = (lane & 3) * 2;

    const int arow = lane & 15;
    const int akoff = (lane >> 4) * 8;
    const int wrow = (lane & 7) + ((lane >> 4) << 3);
    const int wkoff = (lane & 8) ? 8 : 0;

    float acc[2][8][4] = {};

    auto copy_chunk = [&](int kc, int b) {
        uint32_t bb = base + b * PB_BYTES;
        // A: 1024 cp16 over 512 thr = 2/thread
        #pragma unroll
        for (int it = 0; it < 2; ++it) {
            int idx = it * 512 + tid;
            int row = idx >> 2;
            int seg = idx & 3;
            int gr = m0 + row;
            int cr = min(gr, M - 1);
            const __half* src = Ag + (size_t)cr * K + kc * 32 + seg * 8;
            cp16(bb + (uint32_t)(row * 80 + seg * 16), src, (gr < M) ? 16 : 0);
        }
        // W: 512 cp16 = 1/thread
        {
            int row = tid >> 2;
            int seg = tid & 3;
            const __half* src = Wt + (size_t)(n0 + row) * K + kc * 32 + seg * 8;
            cp16(bb + PB_WOFF + (uint32_t)(row * 80 + seg * 16), src, 16);
        }
        asm volatile("cp.async.commit_group;");
    };

    auto compute = [&](int b) {
        uint32_t bb = base + b * PB_BYTES;
        #pragma unroll
        for (int ks = 0; ks < 2; ++ks) {
            int kk = ks * 16;
            uint32_t a[2][4];
            #pragma unroll
            for (int mi = 0; mi < 2; ++mi) {
                uint32_t aoff = bb + (uint32_t)(((wm + mi * 16 + arow) * MMA_LDS + kk + akoff) * 2);
                ldmat_x4(a[mi], aoff);
            }
            #pragma unroll
            for (int nj = 0; nj < 4; ++nj) {
                uint32_t wh[4];
                uint32_t woff = bb + PB_WOFF +
                    (uint32_t)(((wn + nj * 16 + wrow) * MMA_LDS + kk + wkoff) * 2);
                ldmat_x4(wh, woff);
                #pragma unroll
                for (int q = 0; q < 2; ++q)
                    #pragma unroll
                    for (int mi = 0; mi < 2; ++mi)
                        mma16816h(acc[mi][nj * 2 + q], a[mi], wh[q * 2], wh[q * 2 + 1]);
            }
        }
    };

    const int KC = K >> 5;
    copy_chunk(0, 0);
    for (int kc = 0; kc < KC; ++kc) {
        int b = kc & 1;
        if (kc + 1 < KC) {
            copy_chunk(kc + 1, 1 - b);
            asm volatile("cp.async.wait_group 1;");
        } else {
            asm volatile("cp.async.wait_group 0;");
        }
        __syncthreads();
        compute(b);
        __syncthreads();
    }

    // ---- epilogue ----
    #pragma unroll
    for (int mi = 0; mi < 2; ++mi) {
        int r0 = m0 + wm + mi * 16 + g;
        int r1 = r0 + 8;
        float i0 = 1.f, i1 = 1.f, o0 = 1.f, o1 = 1.f;
        if (EPI1) {
            if (r0 < M) { i0 = invin[r0]; o0 = invout[r0]; }
            if (r1 < M) { i1 = invin[r1]; o1 = invout[r1]; }
        }
        #pragma unroll
        for (int ni = 0; ni < 8; ++ni) {
            int col = n0 + wn + ni * 8 + tg2;
            float vx0 = acc[mi][ni][0], vy0 = acc[mi][ni][1];
            float vx1 = acc[mi][ni][2], vy1 = acc[mi][ni][3];
            if (EPI1) {
                float bx = bias[col], by = bias[col + 1];
                vx0 = fmaxf(vx0 * i0 + bx, 0.f) * o0;
                vy0 = fmaxf(vy0 * i0 + by, 0.f) * o0;
                vx1 = fmaxf(vx1 * i1 + bx, 0.f) * o1;
                vy1 = fmaxf(vy1 * i1 + by, 0.f) * o1;
            }
            if (r0 < M)
                *reinterpret_cast<uint32_t*>(Cout + (size_t)r0 * N + col) = pack_h2(vx0, vy0);
            if (r1 < M)
                *reinterpret_cast<uint32_t*>(Cout + (size_t)r1 * N + col) = pack_h2(vx1, vy1);
        }
    }
}

// ============ small GEMM (GEMM3): 128x64 tile, 3 CTA/SM, fp16 1-pass ============
__global__ __launch_bounds__(256, 3)
void mgemm_small_kernel(const __half* __restrict__ Ag,
                        const __half* __restrict__ Wt,
                        __half* __restrict__ Cout,
                        int M, int N, int K) {
    constexpr int TNT = 64;
    constexpr int NI = 4;
    __shared__ __align__(16) __half As[128][MMA_LDS];
    __shared__ __align__(16) __half Ws[TNT][MMA_LDS];

    const int tid = threadIdx.x;
    const int lane = tid & 31;
    const int wid = tid >> 5;
    const int m0 = blockIdx.x * 128;
    const int n0 = blockIdx.y * TNT;
    const int wm = (wid & 3) * 32;
    const int wn = (wid >> 2) * (TNT / 2);
    const int g = lane >> 2;
    const int tg2 = (lane & 3) * 2;

    const int arow = lane & 15;
    const int akoff = (lane >> 4) * 8;
    const int wrow = (lane & 7) + ((lane >> 4) << 3);
    const int wkoff = (lane & 8) ? 8 : 0;

    const uint32_t uA = smem_u32(&As[0][0]);
    const uint32_t uW = smem_u32(&Ws[0][0]);

    float acc[2][NI][4] = {};
    const uint4 z4 = make_uint4(0u, 0u, 0u, 0u);

    for (int k0 = 0; k0 < K; k0 += 32) {
        if (k0 > 0) __syncthreads();
        #pragma unroll
        for (int it = 0; it < 2; ++it) {
            int idx = it * 256 + tid;
            int row = idx >> 2;
            int seg = idx & 3;
            int gr = m0 + row;
            uint4 v = (gr < M)
                ? *reinterpret_cast<const uint4*>(Ag + (size_t)gr * K + k0 + seg * 8) : z4;
            *reinterpret_cast<uint4*>(&As[0][0] + row * MMA_LDS + seg * 8) = v;
        }
        {
            int n = tid >> 2;
            int seg = tid & 3;
            if (n < TNT) {
                int gn = n0 + n;
                uint4 v = z4;
                if (gn < N)
                    v = *reinterpret_cast<const uint4*>(Wt + (size_t)gn * K + k0 + seg * 8);
                *reinterpret_cast<uint4*>(&Ws[0][0] + n * MMA_LDS + seg * 8) = v;
            }
        }
        __syncthreads();

        #pragma unroll
        for (int ks = 0; ks < 2; ++ks) {
            int kk = ks * 16;
            uint32_t a[2][4];
            #pragma unroll
            for (int mi = 0; mi < 2; ++mi) {
                uint32_t aoff = uA + (uint32_t)(((wm + mi * 16 + arow) * MMA_LDS + kk + akoff) * 2);
                ldmat_x4(a[mi], aoff);
            }
            #pragma unroll
            for (int nj = 0; nj < NI / 2; ++nj) {
                uint32_t wh[4];
                uint32_t woff = uW + (uint32_t)(((wn + nj * 16 + wrow) * MMA_LDS + kk + wkoff) * 2);
                ldmat_x4(wh, woff);
                #pragma unroll
                for (int q = 0; q < 2; ++q)
                    #pragma unroll
                    for (int mi = 0; mi < 2; ++mi)
                        mma16816h(acc[mi][nj * 2 + q], a[mi], wh[q * 2], wh[q * 2 + 1]);
            }
        }
    }

    #pragma unroll
    for (int mi = 0; mi < 2; ++mi) {
        int r0 = m0 + wm + mi * 16 + g;
        int r1 = r0 + 8;
        #pragma unroll
        for (int ni = 0; ni < NI; ++ni) {
            int col = n0 + wn + ni * 8 + tg2;
            if (col >= N) continue;
            if (r0 < M)
                *reinterpret_cast<uint32_t*>(Cout + (size_t)r0 * N + col) =
                    pack_h2(acc[mi][ni][0], acc[mi][ni][1]);
            if (r1 < M)
                *reinterpret_cast<uint32_t*>(Cout + (size_t)r1 * N + col) =
                    pack_h2(acc[mi][ni][2], acc[mi][ni][3]);
        }
    }
}

// ---------------- launch ----------------
static inline int cdiv(int a, int b) { return (a + b - 1) / b; }

extern "C" void kernel_launch(void* const* d_in, const int* in_sizes, int n_in,
                              void* d_out, int out_size) {
    const float* feat = (const float*)d_in[0];
    const int*   src  = (const int*)d_in[1];
    const int*   dst  = (const int*)d_in[2];
    const float* W1   = (const float*)d_in[3];
    const float* b1   = (const float*)d_in[4];
    const float* W2   = (const float*)d_in[5];
    const float* b2   = (const float*)d_in[6];
    const float* W3   = (const float*)d_in[7];
    const float* b3   = (const float*)d_in[8];
    const int E = in_sizes[1];
    float* out = (float*)d_out;

    float *invout, *invin;
    int *idegi, *rowstart, *csr;
    __half *a1, *x1, *x2, *feat16, *t2h, *t3h, *wt1, *wt2, *wt3;
    cudaGetSymbolAddress((void**)&a1, g_A1);
    cudaGetSymbolAddress((void**)&x1, g_X1);
    cudaGetSymbolAddress((void**)&x2, g_X2);
    cudaGetSymbolAddress((void**)&feat16, g_feat16);
    cudaGetSymbolAddress((void**)&t2h, g_T2h);
    cudaGetSymbolAddress((void**)&t3h, g_T3h);
    cudaGetSymbolAddress((void**)&invout, g_invout);
    cudaGetSymbolAddress((void**)&invin, g_invin);
    cudaGetSymbolAddress((void**)&idegi, g_idegi);
    cudaGetSymbolAddress((void**)&rowstart, g_rowstart);
    cudaGetSymbolAddress((void**)&csr, g_csr);
    cudaGetSymbolAddress((void**)&wt1, g_Wt1);
    cudaGetSymbolAddress((void**)&wt2, g_Wt2);
    cudaGetSymbolAddress((void**)&wt3, g_Wt3);

    const int T = 256;
    const int MG256 = cdiv(NN, 256);
    const int MG128 = cdiv(NN, 128);
    const int AGG_GRID = cdiv(NN, 8);

    cudaFuncSetAttribute(mgemm256_kernel<true>,
                         cudaFuncAttributeMaxDynamicSharedMemorySize, PB_SMEM);
    cudaFuncSetAttribute(mgemm256_kernel<false>,
                         cudaFuncAttributeMaxDynamicSharedMemorySize, PB_SMEM);

    // build: degrees + scan + CSR + weight fp16 transpose + inv norms + feat prescale
    build_kernel<<<NBLD, TBLD>>>(src, dst, E, W1, W2, W3, feat);

    // ---- Layer 1 ----
    agg128h_kernel<0><<<AGG_GRID, T>>>(feat16, csr, rowstart, idegi,
                                       nullptr, nullptr, nullptr, a1, NN);
    {
        dim3 grid(MG256, 2);
        mgemm256_kernel<true><<<grid, 512, PB_SMEM>>>(a1, wt1, x1,
                                                      NN, 256, 128, invin, b1, invout);
    }

    // ---- Layer 2 ----
    {
        dim3 grid(MG256, 1);
        mgemm256_kernel<false><<<grid, 512, PB_SMEM>>>(x1, wt2, t2h,
                                                       NN, 128, 256, nullptr, nullptr, nullptr);
    }
    agg128h_kernel<1><<<AGG_GRID, T>>>(t2h, csr, rowstart, idegi,
                                       invin, b2, invout, x2, NN);

    // ---- Layer 3 ----
    {
        dim3 grid(MG128, 1);
        mgemm_small_kernel<<<grid, T>>>(x2, wt3, t3h, NN, 40, 128);
    }
    agg40h_kernel<<<AGG_GRID, T>>>(t3h, csr, rowstart, idegi, invin, b3, out, NN);
}